// round 7
// baseline (speedup 1.0000x reference)
#include <cuda_runtime.h>
#include <cuda_fp16.h>
#include <math.h>
#include <stdint.h>

// ---------------- problem constants ----------------
constexpr int B_  = 8;
constexpr int S_  = 4096;
constexpr int D_  = 768;
constexpr int H_  = 12;
constexpr int Wd  = 128;     // window
constexpr int L_  = 2;
constexpr int V_  = 512;
constexpr int FF_ = 3072;
constexpr int DH  = 64;      // D_/H_
constexpr int NB  = S_ / Wd; // 32
constexpr int BSi = B_ * S_; // 32768

// ---------------- scratch (device globals; no allocation allowed) ----------------
__device__ float  g_X  [(size_t)BSi * D_];   // fp32 residual stream
__device__ __half g_XH [(size_t)BSi * D_];   // half copy (GEMM A input)
__device__ float  g_Q  [(size_t)BSi * D_];
__device__ float  g_K  [(size_t)BSi * D_];
__device__ float  g_V  [(size_t)BSi * D_];
__device__ __half g_ATTH[(size_t)BSi * D_];  // attention out (half, feeds Wo)
__device__ float  g_T1 [(size_t)BSi * D_];
__device__ __half g_T1H[(size_t)BSi * D_];
__device__ __half g_HH [(size_t)BSi * FF_];  // FF intermediate (half)
// half weights
__device__ __half g_WHq[(size_t)L_ * D_ * D_];
__device__ __half g_WHk[(size_t)L_ * D_ * D_];
__device__ __half g_WHv[(size_t)L_ * D_ * D_];
__device__ __half g_WHo[(size_t)L_ * D_ * D_];
__device__ __half g_WH1[(size_t)L_ * FF_ * D_];
__device__ __half g_WH2[(size_t)L_ * FF_ * D_];
__device__ __half g_WHc[(size_t)V_ * D_];

// ---------------- helpers ----------------
__device__ __forceinline__ uint32_t smem_u32(const void* p) {
    uint32_t a;
    asm("{ .reg .u64 t; cvta.to.shared.u64 t, %1; cvt.u32.u64 %0, t; }" : "=r"(a) : "l"(p));
    return a;
}
__device__ __forceinline__ float warp_sum(float v) {
    #pragma unroll
    for (int o = 16; o > 0; o >>= 1) v += __shfl_xor_sync(0xffffffffu, v, o);
    return v;
}
__device__ __forceinline__ float warp_max(float v) {
    #pragma unroll
    for (int o = 16; o > 0; o >>= 1) v = fmaxf(v, __shfl_xor_sync(0xffffffffu, v, o));
    return v;
}
__device__ __forceinline__ void mma_f16(float* c, const uint32_t* a, uint32_t b0, uint32_t b1) {
    asm volatile(
        "mma.sync.aligned.m16n8k16.row.col.f32.f16.f16.f32 "
        "{%0,%1,%2,%3}, {%4,%5,%6,%7}, {%8,%9}, {%0,%1,%2,%3};"
        : "+f"(c[0]), "+f"(c[1]), "+f"(c[2]), "+f"(c[3])
        : "r"(a[0]), "r"(a[1]), "r"(a[2]), "r"(a[3]), "r"(b0), "r"(b1));
}
__device__ __forceinline__ void ldsm_x4(uint32_t& r0, uint32_t& r1, uint32_t& r2, uint32_t& r3,
                                        uint32_t addr) {
    asm volatile("ldmatrix.sync.aligned.m8n8.x4.shared.b16 {%0,%1,%2,%3}, [%4];"
        : "=r"(r0), "=r"(r1), "=r"(r2), "=r"(r3) : "r"(addr));
}
#define CP_ASYNC16(dst, src) \
    asm volatile("cp.async.cg.shared.global [%0], [%1], 16;" :: "r"(dst), "l"(src))
#define CP_COMMIT() asm volatile("cp.async.commit_group;" ::: "memory")

typedef unsigned long long u64t;
#define PACK2(d, lo, hi) asm("mov.b64 %0, {%1,%2};" : "=l"(d) : "f"(lo), "f"(hi))
#define UNPACK2(lo, hi, s) asm("mov.b64 {%0,%1}, %2;" : "=f"(lo), "=f"(hi) : "l"(s))
#define FFMA2(d, a, b) asm("fma.rn.f32x2 %0, %1, %2, %0;" : "+l"(d) : "l"(a), "l"(b))
#define FMUL2(d, a, b) asm("mul.rn.f32x2 %0, %1, %2;" : "=l"(d) : "l"(a), "l"(b))

// ================= fp16 tensor-core GEMM (ldmatrix fragments) =================
// C[m,n] = (sum_k A[m,k]*B[n,k] + bias[n]) * alpha, optional ReLU, fp32/fp16 out.
// Tile 128x256x32, 256 threads (8 warps, 2m x 4n, warp tile 64x64),
// 3-stage cp.async ring. Fragments via ldmatrix.x4: per k16 step a warp issues
// 8 LDSM + 32 MMA (vs 32 LDS + 32 MMA before).
constexpr int GTM = 128, GTN = 256, GKC = 32, GSTG = 3;
constexpr int HSTRIDE = 40;                       // halves per smem row
constexpr int A_H = GTM * HSTRIDE;                // 5120 halves
constexpr int B_H = GTN * HSTRIDE;                // 10240 halves
constexpr int STAGE_H = A_H + B_H;                // 15360 halves
constexpr int GEMM_SMEM = GSTG * STAGE_H * 2;     // 92160 bytes

template<bool RELU, bool HOUT>
__global__ void __launch_bounds__(256) gemm_h_kernel(
    const __half* __restrict__ A, const __half* __restrict__ Bw,
    const float* __restrict__ bias, void* __restrict__ Cv,
    int M, int N, int K, float alpha)
{
    extern __shared__ __half smh[];
    const uint32_t sbase = smem_u32(smh);
    const int tid = threadIdx.x, wid = tid >> 5, lane = tid & 31;
    const int g = lane >> 2, tig = lane & 3;
    const int wm = (wid & 1) * 64;
    const int wn = (wid >> 1) * 64;
    const int tile_m = blockIdx.y * GTM, tile_n = blockIdx.x * GTN;

    // ldmatrix lane coordinates: 4 matrices per x4 ->
    //   sel&1 -> +8 rows, sel>>1 -> +8 halves in k
    const int ldrow = (lane & 7) + ((lane >> 3) & 1) * 8;
    const int ldk   = (lane >> 4) * 8;
    // lane-constant half-offsets within a stage
    const uint32_t aOff = (uint32_t)((wm + ldrow) * HSTRIDE + ldk);
    const uint32_t bOff = (uint32_t)(A_H + (wn + ldrow) * HSTRIDE + ldk);

    float c[4][8][4];
    #pragma unroll
    for (int i = 0; i < 4; i++)
        #pragma unroll
        for (int j = 0; j < 8; j++)
            #pragma unroll
            for (int r = 0; r < 4; r++) c[i][j][r] = 0.f;

    const int arow = tid >> 2, ac = tid & 3;

    auto loadStage = [&](int st, int k0) {
        __half* base = smh + st * STAGE_H;
        const __half* Ag = A + (size_t)(tile_m + arow) * K + k0 + ac * 8;
        uint32_t da = smem_u32(base + arow * HSTRIDE + ac * 8);
        CP_ASYNC16(da, Ag);
        CP_ASYNC16(da + 64 * HSTRIDE * 2, Ag + (size_t)64 * K);
        const __half* Bg = Bw + (size_t)(tile_n + arow) * K + k0 + ac * 8;
        uint32_t db = smem_u32(base + A_H + arow * HSTRIDE + ac * 8);
        #pragma unroll
        for (int i = 0; i < 4; i++)
            CP_ASYNC16(db + i * 64 * HSTRIDE * 2, Bg + (size_t)(i * 64) * K);
    };

    auto compute = [&](int st) {
        const uint32_t stBase = sbase + (uint32_t)(st * STAGE_H * 2);
        #pragma unroll
        for (int kk = 0; kk < 2; kk++) {
            uint32_t af[4][4];
            #pragma unroll
            for (int mm = 0; mm < 4; mm++)
                ldsm_x4(af[mm][0], af[mm][1], af[mm][2], af[mm][3],
                        stBase + (aOff + mm * 16 * HSTRIDE + kk * 16) * 2);
            uint32_t bf[4][4];
            #pragma unroll
            for (int np = 0; np < 4; np++)
                ldsm_x4(bf[np][0], bf[np][1], bf[np][2], bf[np][3],
                        stBase + (bOff + np * 16 * HSTRIDE + kk * 16) * 2);
            #pragma unroll
            for (int mm = 0; mm < 4; mm++)
                #pragma unroll
                for (int np = 0; np < 4; np++) {
                    mma_f16(c[mm][2 * np],     af[mm], bf[np][0], bf[np][2]);
                    mma_f16(c[mm][2 * np + 1], af[mm], bf[np][1], bf[np][3]);
                }
        }
    };

    const int NK = K / GKC;
    loadStage(0, 0);   CP_COMMIT();
    loadStage(1, GKC); CP_COMMIT();
    for (int ks = 0; ks < NK; ks++) {
        if (ks + 1 == NK) { asm volatile("cp.async.wait_group 0;" ::: "memory"); }
        else              { asm volatile("cp.async.wait_group 1;" ::: "memory"); }
        __syncthreads();
        compute(ks % 3);
        if (ks + 2 < NK) { loadStage((ks + 2) % 3, (ks + 2) * GKC); CP_COMMIT(); }
    }

    #pragma unroll
    for (int mm = 0; mm < 4; mm++) {
        const int r0 = tile_m + wm + mm * 16 + g;
        #pragma unroll
        for (int nn = 0; nn < 8; nn++) {
            const int col = tile_n + wn + nn * 8 + 2 * tig;
            const float b0 = bias[col], b1 = bias[col + 1];
            float v0 = (c[mm][nn][0] + b0) * alpha;
            float v1 = (c[mm][nn][1] + b1) * alpha;
            float v2 = (c[mm][nn][2] + b0) * alpha;
            float v3 = (c[mm][nn][3] + b1) * alpha;
            if (RELU) {
                v0 = fmaxf(v0, 0.f); v1 = fmaxf(v1, 0.f);
                v2 = fmaxf(v2, 0.f); v3 = fmaxf(v3, 0.f);
            }
            if (HOUT) {
                __half* C = (__half*)Cv;
                *(__half2*)(C + (size_t)r0 * N + col)       = __floats2half2_rn(v0, v1);
                *(__half2*)(C + (size_t)(r0 + 8) * N + col) = __floats2half2_rn(v2, v3);
            } else {
                float* C = (float*)Cv;
                *(float2*)(C + (size_t)r0 * N + col)       = make_float2(v0, v1);
                *(float2*)(C + (size_t)(r0 + 8) * N + col) = make_float2(v2, v3);
            }
        }
    }
}

// ================= weight fp32 -> fp16 conversion =================
__global__ void cvt_f2h_kernel(const float* __restrict__ s, __half* __restrict__ d, int n)
{
    int i = (blockIdx.x * blockDim.x + threadIdx.x) * 4;
    if (i < n) {
        float4 f = *(const float4*)(s + i);
        *(__half2*)(d + i)     = __floats2half2_rn(f.x, f.y);
        *(__half2*)(d + i + 2) = __floats2half2_rn(f.z, f.w);
    }
}

// ================= embedding gather (fp32 + fp16 copies) =================
__global__ void embed_kernel(const int* __restrict__ call,
                             const float* __restrict__ emb,
                             float* __restrict__ X, __half* __restrict__ XH)
{
    size_t row = blockIdx.x;
    int c = call[row];
    const float* src = emb + (size_t)c * D_;
    float*  dst  = X  + row * D_;
    __half* dsth = XH + row * D_;
    for (int d = threadIdx.x; d < D_; d += blockDim.x) {
        float v = src[d];
        dst[d]  = v;
        dsth[d] = __float2half_rn(v);
    }
}

// ================= fused residual add + LayerNorm (fp32 + optional fp16 out) ====
__global__ void __launch_bounds__(256) add_ln_kernel(
    const float* __restrict__ x, const float* __restrict__ a,
    const float* __restrict__ g, const float* __restrict__ beta,
    float* __restrict__ out, __half* __restrict__ outh)
{
    __shared__ float red[8];
    const int row = blockIdx.x;
    const int tid = threadIdx.x;
    const int lane = tid & 31, wid = tid >> 5;
    const float* xr = x + (size_t)row * D_;
    const float* ar = a ? (a + (size_t)row * D_) : nullptr;
    float v[3];
    float s = 0.f;
    #pragma unroll
    for (int i = 0; i < 3; i++) {
        int c = tid + i * 256;
        float val = xr[c];
        if (ar) val += ar[c];
        v[i] = val;
        s += val;
    }
    s = warp_sum(s);
    if (lane == 0) red[wid] = s;
    __syncthreads();
    float tot = 0.f;
    #pragma unroll
    for (int w = 0; w < 8; w++) tot += red[w];
    float mean = tot * (1.f / (float)D_);
    float s2 = 0.f;
    #pragma unroll
    for (int i = 0; i < 3; i++) { float d = v[i] - mean; s2 += d * d; }
    s2 = warp_sum(s2);
    __syncthreads();
    if (lane == 0) red[wid] = s2;
    __syncthreads();
    float tot2 = 0.f;
    #pragma unroll
    for (int w = 0; w < 8; w++) tot2 += red[w];
    float rs = rsqrtf(tot2 * (1.f / (float)D_) + 1e-5f);
    float*  orow = out  ? out  + (size_t)row * D_ : nullptr;
    __half* hrow = outh ? outh + (size_t)row * D_ : nullptr;
    #pragma unroll
    for (int i = 0; i < 3; i++) {
        int c = tid + i * 256;
        float val = (v[i] - mean) * rs * g[c] + beta[c];
        if (orow) orow[c] = val;
        if (hrow) hrow[c] = __float2half_rn(val);
    }
}

// ================= banded attention: chunked smem, warp-uniform iteration ======
constexpr int BCH      = 128;  // keys per chunk
constexpr int BSTRIDE  = 68;   // floats per smem row (16B aligned, padded)
constexpr int SMEM_BAND = 2 * BCH * BSTRIDE * (int)sizeof(float); // 69632

__global__ void __launch_bounds__(128) band_attn_kernel(
    const float* __restrict__ Qf, const float* __restrict__ Kf,
    const float* __restrict__ Vf, __half* __restrict__ O)
{
    extern __shared__ float smb[];
    float* Ks = smb;
    float* Vs = smb + BCH * BSTRIDE;

    const int n = blockIdx.x, h = blockIdx.y, b = blockIdx.z;
    const int i = threadIdx.x;
    const int qpos = n * Wd + i;

    u64t q2[32], acc2[32];
    {
        const ulonglong2* qp = (const ulonglong2*)(Qf + (((size_t)b * S_ + qpos) * H_ + h) * DH);
        #pragma unroll
        for (int c = 0; c < 16; c++) { ulonglong2 t = qp[c]; q2[2*c] = t.x; q2[2*c+1] = t.y; }
    }
    #pragma unroll
    for (int k = 0; k < 32; k++) acc2[k] = 0ull;
    float m = -1e30f, ssum = 0.f;

    // ---- global key 0 first (direct LDG, all lanes same row -> broadcast) ----
    {
        const ulonglong2* kr = (const ulonglong2*)(Kf + ((size_t)b * S_ * H_ + h) * DH);
        const ulonglong2* vr = (const ulonglong2*)(Vf + ((size_t)b * S_ * H_ + h) * DH);
        u64t s2 = 0ull;
        #pragma unroll
        for (int c = 0; c < 16; c++) {
            ulonglong2 kv = kr[c];
            FFMA2(s2, q2[2*c], kv.x);
            FFMA2(s2, q2[2*c+1], kv.y);
        }
        float sa, sb;
        UNPACK2(sa, sb, s2);
        float s = sa + sb;          // no bias on the global column
        m = s; ssum = 1.f;          // first key: p = 1
        #pragma unroll
        for (int c = 0; c < 16; c++) {
            ulonglong2 vv = vr[c];
            float lo, hi;
            UNPACK2(lo, hi, vv.x); PACK2(acc2[2*c],   lo, hi);
            UNPACK2(lo, hi, vv.y); PACK2(acc2[2*c+1], lo, hi);
        }
    }

    const int base = n * Wd - Wd;
    int lo = i, hi = i + 2 * Wd;
    if (n == 0 && lo < Wd) lo = Wd;
    if (hi > 383) hi = 383;
    if (n == NB - 1 && hi > 255) hi = 255;

    for (int c = 0; c < 3; c++) {
        if (n == 0 && c == 0) continue;
        if (n == NB - 1 && c == 2) continue;
        const int clo = c * BCH;
        __syncthreads();
        for (int t = i; t < BCH * 16; t += 128) {
            int row = t >> 4, col = t & 15;
            size_t gb = (((size_t)b * S_ + (base + clo + row)) * H_ + h) * DH + col * 4;
            *(float4*)(Ks + row * BSTRIDE + col * 4) = *(const float4*)(Kf + gb);
            *(float4*)(Vs + row * BSTRIDE + col * 4) = *(const float4*)(Vf + gb);
        }
        __syncthreads();

        int llo = lo > clo ? lo : clo;
        int lhi = hi < clo + BCH - 1 ? hi : clo + BCH - 1;
        int wlo = __shfl_sync(0xffffffffu, llo, 0);
        int whi = __shfl_sync(0xffffffffu, lhi, 31);
        for (int jj = wlo; jj <= whi; jj++) {
            if (jj < llo || jj > lhi) continue;
            const int row = jj - clo;
            const int pos = base + jj;
            const ulonglong2* kr = (const ulonglong2*)(Ks + row * BSTRIDE);
            u64t s2 = 0ull;
            #pragma unroll
            for (int cc = 0; cc < 16; cc++) {
                ulonglong2 kv = kr[cc];
                FFMA2(s2, q2[2*cc], kv.x);
                FFMA2(s2, q2[2*cc+1], kv.y);
            }
            float sa, sb;
            UNPACK2(sa, sb, s2);
            float s = sa + sb + ((pos == 0) ? -10000.f : 0.f);
            if (s > m) {
                float corr = __expf(m - s);
                u64t cc2; PACK2(cc2, corr, corr);
                ssum *= corr;
                #pragma unroll
                for (int k = 0; k < 32; k++) FMUL2(acc2[k], acc2[k], cc2);
                m = s;
            }
            float p = __expf(s - m);
            ssum += p;
            u64t pp; PACK2(pp, p, p);
            const ulonglong2* vr = (const ulonglong2*)(Vs + row * BSTRIDE);
            #pragma unroll
            for (int cc = 0; cc < 16; cc++) {
                ulonglong2 vv = vr[cc];
                FFMA2(acc2[2*cc],   pp, vv.x);
                FFMA2(acc2[2*cc+1], pp, vv.y);
            }
        }
    }

    float inv = 1.f / ssum;
    __half* op = O + (((size_t)b * S_ + qpos) * H_ + h) * DH;
    #pragma unroll
    for (int c = 0; c < 32; c++) {
        float lo2, hi2;
        UNPACK2(lo2, hi2, acc2[c]);
        *(__half2*)(op + 2 * c) = __floats2half2_rn(lo2 * inv, hi2 * inv);
    }
}

// ================= full attention for the global query (s = 0) =================
__global__ void __launch_bounds__(512) global_attn_kernel(
    const float* __restrict__ Q, const float* __restrict__ Kt,
    const float* __restrict__ Vt, __half* __restrict__ O)
{
    __shared__ float qs[DH];
    __shared__ float sc[S_];
    __shared__ float red[16];
    __shared__ float ob[512];
    const int h = blockIdx.x, b = blockIdx.y;
    const int tid = threadIdx.x;
    const int lane = tid & 31, wid = tid >> 5;
    if (tid < DH) qs[tid] = Q[(((size_t)b * S_) * H_ + h) * DH + tid];
    __syncthreads();
    float lm = -1e30f;
    for (int s = tid; s < S_; s += 512) {
        const float* kp = Kt + (((size_t)b * S_ + s) * H_ + h) * DH;
        float d0 = 0.f, d1 = 0.f, d2 = 0.f, d3 = 0.f;
        #pragma unroll
        for (int c = 0; c < 16; c++) {
            d0 = fmaf(qs[c*4+0], kp[c*4+0], d0); d1 = fmaf(qs[c*4+1], kp[c*4+1], d1);
            d2 = fmaf(qs[c*4+2], kp[c*4+2], d2); d3 = fmaf(qs[c*4+3], kp[c*4+3], d3);
        }
        float sv = (d0 + d1) + (d2 + d3);
        sc[s] = sv;
        lm = fmaxf(lm, sv);
    }
    lm = warp_max(lm);
    if (lane == 0) red[wid] = lm;
    __syncthreads();
    float gm = -1e30f;
    #pragma unroll
    for (int w = 0; w < 16; w++) gm = fmaxf(gm, red[w]);
    float ls = 0.f;
    for (int s = tid; s < S_; s += 512) {
        float p = __expf(sc[s] - gm);
        sc[s] = p;
        ls += p;
    }
    ls = warp_sum(ls);
    __syncthreads();
    if (lane == 0) red[wid] = ls;
    __syncthreads();
    float gs = 0.f;
    #pragma unroll
    for (int w = 0; w < 16; w++) gs += red[w];
    const int d = tid & 63, seg = tid >> 6;
    float acc = 0.f;
    const int s0 = seg * (S_ / 8), s1 = s0 + (S_ / 8);
    for (int s = s0; s < s1; s++)
        acc = fmaf(sc[s], Vt[(((size_t)b * S_ + s) * H_ + h) * DH + d], acc);
    ob[tid] = acc;
    __syncthreads();
    if (tid < DH) {
        float tot = 0.f;
        #pragma unroll
        for (int k = 0; k < 8; k++) tot += ob[d + 64 * k];
        O[(((size_t)b * S_) * H_ + h) * DH + tid] = __float2half_rn(tot / gs);
    }
}

// ================= host side =================
static void gemm_h(const __half* A, const __half* Bw, const float* bias, void* C,
                   int M, int N, int K, float alpha, bool relu, bool hout)
{
    dim3 grid(N / GTN, M / GTM);
    if (relu) {
        if (hout) gemm_h_kernel<true, true ><<<grid, 256, GEMM_SMEM>>>(A, Bw, bias, C, M, N, K, alpha);
        else      gemm_h_kernel<true, false><<<grid, 256, GEMM_SMEM>>>(A, Bw, bias, C, M, N, K, alpha);
    } else {
        if (hout) gemm_h_kernel<false, true ><<<grid, 256, GEMM_SMEM>>>(A, Bw, bias, C, M, N, K, alpha);
        else      gemm_h_kernel<false, false><<<grid, 256, GEMM_SMEM>>>(A, Bw, bias, C, M, N, K, alpha);
    }
}

static void cvt(const float* s, __half* d, size_t n) {
    int blocks = (int)((n / 4 + 255) / 256);
    cvt_f2h_kernel<<<blocks, 256>>>(s, d, (int)n);
}

extern "C" void kernel_launch(void* const* d_in, const int* in_sizes, int n_in,
                              void* d_out, int out_size)
{
    const int* call = (const int*)d_in[0];

    int e = 9;
    for (int i = 0; i < n_in; i++) {
        if (in_sizes[i] == V_ * D_) { e = i; break; }
    }
    const float* emb   = (const float*)d_in[e + 0];
    const float* Wq    = (const float*)d_in[e + 1];
    const float* bq    = (const float*)d_in[e + 2];
    const float* Wk    = (const float*)d_in[e + 3];
    const float* bk    = (const float*)d_in[e + 4];
    const float* Wv    = (const float*)d_in[e + 5];
    const float* bv    = (const float*)d_in[e + 6];
    const float* Wo    = (const float*)d_in[e + 7];
    const float* bo    = (const float*)d_in[e + 8];
    const float* W1    = (const float*)d_in[e + 9];
    const float* b1    = (const float*)d_in[e + 10];
    const float* W2    = (const float*)d_in[e + 11];
    const float* b2    = (const float*)d_in[e + 12];
    const float* g1    = (const float*)d_in[e + 13];
    const float* beta1 = (const float*)d_in[e + 14];
    const float* g2    = (const float*)d_in[e + 15];
    const float* beta2 = (const float*)d_in[e + 16];
    const float* gf    = (const float*)d_in[e + 17];
    const float* betaf = (const float*)d_in[e + 18];
    const float* Wc    = (const float*)d_in[e + 19];
    const float* bc    = (const float*)d_in[e + 20];
    float* out = (float*)d_out;

    float *X, *Qb, *Kb, *Vb, *T1;
    __half *XH, *ATTH, *T1H, *HH, *WHq, *WHk, *WHv, *WHo, *WH1, *WH2, *WHc;
    cudaGetSymbolAddress((void**)&X,    g_X);
    cudaGetSymbolAddress((void**)&XH,   g_XH);
    cudaGetSymbolAddress((void**)&Qb,   g_Q);
    cudaGetSymbolAddress((void**)&Kb,   g_K);
    cudaGetSymbolAddress((void**)&Vb,   g_V);
    cudaGetSymbolAddress((void**)&ATTH, g_ATTH);
    cudaGetSymbolAddress((void**)&T1,   g_T1);
    cudaGetSymbolAddress((void**)&T1H,  g_T1H);
    cudaGetSymbolAddress((void**)&HH,   g_HH);
    cudaGetSymbolAddress((void**)&WHq,  g_WHq);
    cudaGetSymbolAddress((void**)&WHk,  g_WHk);
    cudaGetSymbolAddress((void**)&WHv,  g_WHv);
    cudaGetSymbolAddress((void**)&WHo,  g_WHo);
    cudaGetSymbolAddress((void**)&WH1,  g_WH1);
    cudaGetSymbolAddress((void**)&WH2,  g_WH2);
    cudaGetSymbolAddress((void**)&WHc,  g_WHc);

    cudaFuncSetAttribute(gemm_h_kernel<false, false>,
                         cudaFuncAttributeMaxDynamicSharedMemorySize, GEMM_SMEM);
    cudaFuncSetAttribute(gemm_h_kernel<false, true>,
                         cudaFuncAttributeMaxDynamicSharedMemorySize, GEMM_SMEM);
    cudaFuncSetAttribute(gemm_h_kernel<true, false>,
                         cudaFuncAttributeMaxDynamicSharedMemorySize, GEMM_SMEM);
    cudaFuncSetAttribute(gemm_h_kernel<true, true>,
                         cudaFuncAttributeMaxDynamicSharedMemorySize, GEMM_SMEM);
    cudaFuncSetAttribute(band_attn_kernel,
                         cudaFuncAttributeMaxDynamicSharedMemorySize, SMEM_BAND);

    // weights -> fp16 (RNE)
    cvt(Wq, WHq, (size_t)L_ * D_ * D_);
    cvt(Wk, WHk, (size_t)L_ * D_ * D_);
    cvt(Wv, WHv, (size_t)L_ * D_ * D_);
    cvt(Wo, WHo, (size_t)L_ * D_ * D_);
    cvt(W1, WH1, (size_t)L_ * FF_ * D_);
    cvt(W2, WH2, (size_t)L_ * FF_ * D_);
    cvt(Wc, WHc, (size_t)V_ * D_);

    embed_kernel<<<BSi, 256>>>(call, emb, X, XH);

    const dim3 gAttn(NB, H_, B_);
    const dim3 gGlob(H_, B_);
    const size_t DD = (size_t)D_ * D_;
    const size_t FD = (size_t)FF_ * D_;

    for (int l = 0; l < L_; l++) {
        gemm_h(XH, WHq + l * DD, bq + l * D_, Qb, BSi, D_, D_, 0.125f, false, false);
        gemm_h(XH, WHk + l * DD, bk + l * D_, Kb, BSi, D_, D_, 1.f, false, false);
        gemm_h(XH, WHv + l * DD, bv + l * D_, Vb, BSi, D_, D_, 1.f, false, false);

        band_attn_kernel<<<gAttn, 128, SMEM_BAND>>>(Qb, Kb, Vb, ATTH);
        global_attn_kernel<<<gGlob, 512>>>(Qb, Kb, Vb, ATTH);

        gemm_h(ATTH, WHo + l * DD, bo + l * D_, T1, BSi, D_, D_, 1.f, false, false);
        add_ln_kernel<<<BSi, 256>>>(X, T1, g1 + l * D_, beta1 + l * D_, X, XH);

        gemm_h(XH, WH1 + l * FD, b1 + l * FF_, HH, BSi, FF_, D_, 1.f, true, true);
        gemm_h(HH, WH2 + l * FD, b2 + l * D_, T1, BSi, D_, FF_, 1.f, false, false);
        add_ln_kernel<<<BSi, 256>>>(X, T1, g2 + l * D_, beta2 + l * D_, X, XH);
    }

    add_ln_kernel<<<BSi, 256>>>(X, nullptr, gf, betaf, nullptr, T1H);
    gemm_h(T1H, WHc, bc, out, BSi, V_, D_, 1.f, false, false);
}

// round 8
// speedup vs baseline: 1.0392x; 1.0392x over previous
#include <cuda_runtime.h>
#include <cuda_fp16.h>
#include <math.h>
#include <stdint.h>

// ---------------- problem constants ----------------
constexpr int B_  = 8;
constexpr int S_  = 4096;
constexpr int D_  = 768;
constexpr int H_  = 12;
constexpr int Wd  = 128;     // window
constexpr int L_  = 2;
constexpr int V_  = 512;
constexpr int FF_ = 3072;
constexpr int DH  = 64;      // D_/H_
constexpr int NB  = S_ / Wd; // 32
constexpr int BSi = B_ * S_; // 32768

// ---------------- scratch (device globals; no allocation allowed) ----------------
__device__ float  g_X  [(size_t)BSi * D_];   // fp32 residual stream
__device__ __half g_XH [(size_t)BSi * D_];   // half copy (GEMM A input)
__device__ float  g_Q  [(size_t)BSi * D_];
__device__ float  g_K  [(size_t)BSi * D_];
__device__ float  g_V  [(size_t)BSi * D_];
__device__ __half g_ATTH[(size_t)BSi * D_];  // attention out (half, feeds Wo)
__device__ float  g_T1 [(size_t)BSi * D_];
__device__ __half g_T1H[(size_t)BSi * D_];
__device__ __half g_HH [(size_t)BSi * FF_];  // FF intermediate (half)
// half weights
__device__ __half g_WHq[(size_t)L_ * D_ * D_];
__device__ __half g_WHk[(size_t)L_ * D_ * D_];
__device__ __half g_WHv[(size_t)L_ * D_ * D_];
__device__ __half g_WHo[(size_t)L_ * D_ * D_];
__device__ __half g_WH1[(size_t)L_ * FF_ * D_];
__device__ __half g_WH2[(size_t)L_ * FF_ * D_];
__device__ __half g_WHc[(size_t)V_ * D_];

// ---------------- helpers ----------------
__device__ __forceinline__ uint32_t smem_u32(const void* p) {
    uint32_t a;
    asm("{ .reg .u64 t; cvta.to.shared.u64 t, %1; cvt.u32.u64 %0, t; }" : "=r"(a) : "l"(p));
    return a;
}
__device__ __forceinline__ float warp_sum(float v) {
    #pragma unroll
    for (int o = 16; o > 0; o >>= 1) v += __shfl_xor_sync(0xffffffffu, v, o);
    return v;
}
__device__ __forceinline__ float warp_max(float v) {
    #pragma unroll
    for (int o = 16; o > 0; o >>= 1) v = fmaxf(v, __shfl_xor_sync(0xffffffffu, v, o));
    return v;
}
__device__ __forceinline__ void mma_f16(float* c, const uint32_t* a, const uint32_t* b) {
    asm volatile(
        "mma.sync.aligned.m16n8k16.row.col.f32.f16.f16.f32 "
        "{%0,%1,%2,%3}, {%4,%5,%6,%7}, {%8,%9}, {%0,%1,%2,%3};"
        : "+f"(c[0]), "+f"(c[1]), "+f"(c[2]), "+f"(c[3])
        : "r"(a[0]), "r"(a[1]), "r"(a[2]), "r"(a[3]), "r"(b[0]), "r"(b[1]));
}
#define CP_ASYNC16(dst, src) \
    asm volatile("cp.async.cg.shared.global [%0], [%1], 16;" :: "r"(dst), "l"(src))
#define CP_COMMIT() asm volatile("cp.async.commit_group;" ::: "memory")

typedef unsigned long long u64t;
#define PACK2(d, lo, hi) asm("mov.b64 %0, {%1,%2};" : "=l"(d) : "f"(lo), "f"(hi))
#define UNPACK2(lo, hi, s) asm("mov.b64 {%0,%1}, %2;" : "=f"(lo), "=f"(hi) : "l"(s))
#define FFMA2(d, a, b) asm("fma.rn.f32x2 %0, %1, %2, %0;" : "+l"(d) : "l"(a), "l"(b))
#define FMUL2(d, a, b) asm("mul.rn.f32x2 %0, %1, %2;" : "=l"(d) : "l"(a), "l"(b))

// ================= fp16 tensor-core GEMM =================
// C[m,n] = (sum_k A[m,k]*B[n,k] + bias[n]) * alpha, optional ReLU, fp32/fp16 out.
// Tile 128x256x32, 512 threads (16 warps, 4m x 4n, warp tile 32x64),
// 3-stage cp.async ring. 16 warps/SM (4 per SMSP) for latency hiding;
// scalar LDS fragments (proven conflict-free with HSTRIDE=40).
constexpr int GTM = 128, GTN = 256, GKC = 32, GSTG = 3;
constexpr int HSTRIDE = 40;                       // halves per smem row
constexpr int A_H = GTM * HSTRIDE;                // 5120 halves
constexpr int B_H = GTN * HSTRIDE;                // 10240 halves
constexpr int STAGE_H = A_H + B_H;                // 15360 halves
constexpr int GEMM_SMEM = GSTG * STAGE_H * 2;     // 92160 bytes

template<bool RELU, bool HOUT>
__global__ void __launch_bounds__(512) gemm_h_kernel(
    const __half* __restrict__ A, const __half* __restrict__ Bw,
    const float* __restrict__ bias, void* __restrict__ Cv,
    int M, int N, int K, float alpha)
{
    extern __shared__ __half smh[];
    const int tid = threadIdx.x, wid = tid >> 5, lane = tid & 31;
    const int g = lane >> 2, tig = lane & 3;
    const int wm = (wid & 3) * 32;       // 4 warps along m
    const int wn = (wid >> 2) * 64;      // 4 warps along n
    const int tile_m = blockIdx.y * GTM, tile_n = blockIdx.x * GTN;

    float c[2][8][4];
    #pragma unroll
    for (int i = 0; i < 2; i++)
        #pragma unroll
        for (int j = 0; j < 8; j++)
            #pragma unroll
            for (int r = 0; r < 4; r++) c[i][j][r] = 0.f;

    const int srow = tid >> 2, sc4 = tid & 3;   // staging: 512 chunks of 16B

    auto loadStage = [&](int st, int k0) {
        __half* base = smh + st * STAGE_H;
        const __half* Ag = A + (size_t)(tile_m + srow) * K + k0 + sc4 * 8;
        CP_ASYNC16(smem_u32(base + srow * HSTRIDE + sc4 * 8), Ag);
        const __half* Bg = Bw + (size_t)(tile_n + srow) * K + k0 + sc4 * 8;
        uint32_t db = smem_u32(base + A_H + srow * HSTRIDE + sc4 * 8);
        CP_ASYNC16(db, Bg);
        CP_ASYNC16(db + 128 * HSTRIDE * 2, Bg + (size_t)128 * K);
    };

    auto compute = [&](int st) {
        const uint32_t* Aw = (const uint32_t*)(smh + st * STAGE_H);
        const uint32_t* Bv = (const uint32_t*)(smh + st * STAGE_H + A_H);
        #pragma unroll
        for (int kk = 0; kk < 2; kk++) {
            uint32_t af[2][4], bf[8][2];
            #pragma unroll
            for (int mm = 0; mm < 2; mm++) {
                const uint32_t* p = Aw + (wm + mm * 16 + g) * 20 + kk * 8 + tig;
                af[mm][0] = p[0];
                af[mm][1] = p[8 * 20];
                af[mm][2] = p[4];
                af[mm][3] = p[8 * 20 + 4];
            }
            #pragma unroll
            for (int nn = 0; nn < 8; nn++) {
                const uint32_t* p = Bv + (wn + nn * 8 + g) * 20 + kk * 8 + tig;
                bf[nn][0] = p[0];
                bf[nn][1] = p[4];
            }
            #pragma unroll
            for (int mm = 0; mm < 2; mm++)
                #pragma unroll
                for (int nn = 0; nn < 8; nn++)
                    mma_f16(c[mm][nn], af[mm], bf[nn]);
        }
    };

    const int NK = K / GKC;
    loadStage(0, 0);   CP_COMMIT();
    loadStage(1, GKC); CP_COMMIT();
    for (int ks = 0; ks < NK; ks++) {
        if (ks + 1 == NK) { asm volatile("cp.async.wait_group 0;" ::: "memory"); }
        else              { asm volatile("cp.async.wait_group 1;" ::: "memory"); }
        __syncthreads();
        compute(ks % 3);
        if (ks + 2 < NK) { loadStage((ks + 2) % 3, (ks + 2) * GKC); CP_COMMIT(); }
    }

    #pragma unroll
    for (int mm = 0; mm < 2; mm++) {
        const int r0 = tile_m + wm + mm * 16 + g;
        #pragma unroll
        for (int nn = 0; nn < 8; nn++) {
            const int col = tile_n + wn + nn * 8 + 2 * tig;
            const float b0 = bias[col], b1 = bias[col + 1];
            float v0 = (c[mm][nn][0] + b0) * alpha;
            float v1 = (c[mm][nn][1] + b1) * alpha;
            float v2 = (c[mm][nn][2] + b0) * alpha;
            float v3 = (c[mm][nn][3] + b1) * alpha;
            if (RELU) {
                v0 = fmaxf(v0, 0.f); v1 = fmaxf(v1, 0.f);
                v2 = fmaxf(v2, 0.f); v3 = fmaxf(v3, 0.f);
            }
            if (HOUT) {
                __half* C = (__half*)Cv;
                *(__half2*)(C + (size_t)r0 * N + col)       = __floats2half2_rn(v0, v1);
                *(__half2*)(C + (size_t)(r0 + 8) * N + col) = __floats2half2_rn(v2, v3);
            } else {
                float* C = (float*)Cv;
                *(float2*)(C + (size_t)r0 * N + col)       = make_float2(v0, v1);
                *(float2*)(C + (size_t)(r0 + 8) * N + col) = make_float2(v2, v3);
            }
        }
    }
}

// ================= weight fp32 -> fp16 conversion =================
__global__ void cvt_f2h_kernel(const float* __restrict__ s, __half* __restrict__ d, int n)
{
    int i = (blockIdx.x * blockDim.x + threadIdx.x) * 4;
    if (i < n) {
        float4 f = *(const float4*)(s + i);
        *(__half2*)(d + i)     = __floats2half2_rn(f.x, f.y);
        *(__half2*)(d + i + 2) = __floats2half2_rn(f.z, f.w);
    }
}

// ================= embedding gather (fp32 + fp16 copies) =================
__global__ void embed_kernel(const int* __restrict__ call,
                             const float* __restrict__ emb,
                             float* __restrict__ X, __half* __restrict__ XH)
{
    size_t row = blockIdx.x;
    int c = call[row];
    const float* src = emb + (size_t)c * D_;
    float*  dst  = X  + row * D_;
    __half* dsth = XH + row * D_;
    for (int d = threadIdx.x; d < D_; d += blockDim.x) {
        float v = src[d];
        dst[d]  = v;
        dsth[d] = __float2half_rn(v);
    }
}

// ================= fused residual add + LayerNorm (fp32 + optional fp16 out) ====
__global__ void __launch_bounds__(256) add_ln_kernel(
    const float* __restrict__ x, const float* __restrict__ a,
    const float* __restrict__ g, const float* __restrict__ beta,
    float* __restrict__ out, __half* __restrict__ outh)
{
    __shared__ float red[8];
    const int row = blockIdx.x;
    const int tid = threadIdx.x;
    const int lane = tid & 31, wid = tid >> 5;
    const float* xr = x + (size_t)row * D_;
    const float* ar = a ? (a + (size_t)row * D_) : nullptr;
    float v[3];
    float s = 0.f;
    #pragma unroll
    for (int i = 0; i < 3; i++) {
        int c = tid + i * 256;
        float val = xr[c];
        if (ar) val += ar[c];
        v[i] = val;
        s += val;
    }
    s = warp_sum(s);
    if (lane == 0) red[wid] = s;
    __syncthreads();
    float tot = 0.f;
    #pragma unroll
    for (int w = 0; w < 8; w++) tot += red[w];
    float mean = tot * (1.f / (float)D_);
    float s2 = 0.f;
    #pragma unroll
    for (int i = 0; i < 3; i++) { float d = v[i] - mean; s2 += d * d; }
    s2 = warp_sum(s2);
    __syncthreads();
    if (lane == 0) red[wid] = s2;
    __syncthreads();
    float tot2 = 0.f;
    #pragma unroll
    for (int w = 0; w < 8; w++) tot2 += red[w];
    float rs = rsqrtf(tot2 * (1.f / (float)D_) + 1e-5f);
    float*  orow = out  ? out  + (size_t)row * D_ : nullptr;
    __half* hrow = outh ? outh + (size_t)row * D_ : nullptr;
    #pragma unroll
    for (int i = 0; i < 3; i++) {
        int c = tid + i * 256;
        float val = (v[i] - mean) * rs * g[c] + beta[c];
        if (orow) orow[c] = val;
        if (hrow) hrow[c] = __float2half_rn(val);
    }
}

// ================= banded attention: chunked smem, warp-uniform iteration ======
constexpr int BCH      = 128;  // keys per chunk
constexpr int BSTRIDE  = 68;   // floats per smem row (16B aligned, padded)
constexpr int SMEM_BAND = 2 * BCH * BSTRIDE * (int)sizeof(float); // 69632

__global__ void __launch_bounds__(128) band_attn_kernel(
    const float* __restrict__ Qf, const float* __restrict__ Kf,
    const float* __restrict__ Vf, __half* __restrict__ O)
{
    extern __shared__ float smb[];
    float* Ks = smb;
    float* Vs = smb + BCH * BSTRIDE;

    const int n = blockIdx.x, h = blockIdx.y, b = blockIdx.z;
    const int i = threadIdx.x;
    const int qpos = n * Wd + i;

    u64t q2[32], acc2[32];
    {
        const ulonglong2* qp = (const ulonglong2*)(Qf + (((size_t)b * S_ + qpos) * H_ + h) * DH);
        #pragma unroll
        for (int c = 0; c < 16; c++) { ulonglong2 t = qp[c]; q2[2*c] = t.x; q2[2*c+1] = t.y; }
    }
    #pragma unroll
    for (int k = 0; k < 32; k++) acc2[k] = 0ull;
    float m = -1e30f, ssum = 0.f;

    // ---- global key 0 first (direct LDG, all lanes same row -> broadcast) ----
    {
        const ulonglong2* kr = (const ulonglong2*)(Kf + ((size_t)b * S_ * H_ + h) * DH);
        const ulonglong2* vr = (const ulonglong2*)(Vf + ((size_t)b * S_ * H_ + h) * DH);
        u64t s2 = 0ull;
        #pragma unroll
        for (int c = 0; c < 16; c++) {
            ulonglong2 kv = kr[c];
            FFMA2(s2, q2[2*c], kv.x);
            FFMA2(s2, q2[2*c+1], kv.y);
        }
        float sa, sb;
        UNPACK2(sa, sb, s2);
        float s = sa + sb;          // no bias on the global column
        m = s; ssum = 1.f;          // first key: p = 1
        #pragma unroll
        for (int c = 0; c < 16; c++) {
            ulonglong2 vv = vr[c];
            float lo, hi;
            UNPACK2(lo, hi, vv.x); PACK2(acc2[2*c],   lo, hi);
            UNPACK2(lo, hi, vv.y); PACK2(acc2[2*c+1], lo, hi);
        }
    }

    const int base = n * Wd - Wd;
    int lo = i, hi = i + 2 * Wd;
    if (n == 0 && lo < Wd) lo = Wd;
    if (hi > 383) hi = 383;
    if (n == NB - 1 && hi > 255) hi = 255;

    for (int c = 0; c < 3; c++) {
        if (n == 0 && c == 0) continue;
        if (n == NB - 1 && c == 2) continue;
        const int clo = c * BCH;
        __syncthreads();
        for (int t = i; t < BCH * 16; t += 128) {
            int row = t >> 4, col = t & 15;
            size_t gb = (((size_t)b * S_ + (base + clo + row)) * H_ + h) * DH + col * 4;
            *(float4*)(Ks + row * BSTRIDE + col * 4) = *(const float4*)(Kf + gb);
            *(float4*)(Vs + row * BSTRIDE + col * 4) = *(const float4*)(Vf + gb);
        }
        __syncthreads();

        int llo = lo > clo ? lo : clo;
        int lhi = hi < clo + BCH - 1 ? hi : clo + BCH - 1;
        int wlo = __shfl_sync(0xffffffffu, llo, 0);
        int whi = __shfl_sync(0xffffffffu, lhi, 31);
        for (int jj = wlo; jj <= whi; jj++) {
            if (jj < llo || jj > lhi) continue;
            const int row = jj - clo;
            const int pos = base + jj;
            const ulonglong2* kr = (const ulonglong2*)(Ks + row * BSTRIDE);
            u64t s2 = 0ull;
            #pragma unroll
            for (int cc = 0; cc < 16; cc++) {
                ulonglong2 kv = kr[cc];
                FFMA2(s2, q2[2*cc], kv.x);
                FFMA2(s2, q2[2*cc+1], kv.y);
            }
            float sa, sb;
            UNPACK2(sa, sb, s2);
            float s = sa + sb + ((pos == 0) ? -10000.f : 0.f);
            if (s > m) {
                float corr = __expf(m - s);
                u64t cc2; PACK2(cc2, corr, corr);
                ssum *= corr;
                #pragma unroll
                for (int k = 0; k < 32; k++) FMUL2(acc2[k], acc2[k], cc2);
                m = s;
            }
            float p = __expf(s - m);
            ssum += p;
            u64t pp; PACK2(pp, p, p);
            const ulonglong2* vr = (const ulonglong2*)(Vs + row * BSTRIDE);
            #pragma unroll
            for (int cc = 0; cc < 16; cc++) {
                ulonglong2 vv = vr[cc];
                FFMA2(acc2[2*cc],   pp, vv.x);
                FFMA2(acc2[2*cc+1], pp, vv.y);
            }
        }
    }

    float inv = 1.f / ssum;
    __half* op = O + (((size_t)b * S_ + qpos) * H_ + h) * DH;
    #pragma unroll
    for (int c = 0; c < 32; c++) {
        float lo2, hi2;
        UNPACK2(lo2, hi2, acc2[c]);
        *(__half2*)(op + 2 * c) = __floats2half2_rn(lo2 * inv, hi2 * inv);
    }
}

// ================= full attention for the global query (s = 0) =================
__global__ void __launch_bounds__(512) global_attn_kernel(
    const float* __restrict__ Q, const float* __restrict__ Kt,
    const float* __restrict__ Vt, __half* __restrict__ O)
{
    __shared__ float qs[DH];
    __shared__ float sc[S_];
    __shared__ float red[16];
    __shared__ float ob[512];
    const int h = blockIdx.x, b = blockIdx.y;
    const int tid = threadIdx.x;
    const int lane = tid & 31, wid = tid >> 5;
    if (tid < DH) qs[tid] = Q[(((size_t)b * S_) * H_ + h) * DH + tid];
    __syncthreads();
    float lm = -1e30f;
    for (int s = tid; s < S_; s += 512) {
        const float* kp = Kt + (((size_t)b * S_ + s) * H_ + h) * DH;
        float d0 = 0.f, d1 = 0.f, d2 = 0.f, d3 = 0.f;
        #pragma unroll
        for (int c = 0; c < 16; c++) {
            d0 = fmaf(qs[c*4+0], kp[c*4+0], d0); d1 = fmaf(qs[c*4+1], kp[c*4+1], d1);
            d2 = fmaf(qs[c*4+2], kp[c*4+2], d2); d3 = fmaf(qs[c*4+3], kp[c*4+3], d3);
        }
        float sv = (d0 + d1) + (d2 + d3);
        sc[s] = sv;
        lm = fmaxf(lm, sv);
    }
    lm = warp_max(lm);
    if (lane == 0) red[wid] = lm;
    __syncthreads();
    float gm = -1e30f;
    #pragma unroll
    for (int w = 0; w < 16; w++) gm = fmaxf(gm, red[w]);
    float ls = 0.f;
    for (int s = tid; s < S_; s += 512) {
        float p = __expf(sc[s] - gm);
        sc[s] = p;
        ls += p;
    }
    ls = warp_sum(ls);
    __syncthreads();
    if (lane == 0) red[wid] = ls;
    __syncthreads();
    float gs = 0.f;
    #pragma unroll
    for (int w = 0; w < 16; w++) gs += red[w];
    const int d = tid & 63, seg = tid >> 6;
    float acc = 0.f;
    const int s0 = seg * (S_ / 8), s1 = s0 + (S_ / 8);
    for (int s = s0; s < s1; s++)
        acc = fmaf(sc[s], Vt[(((size_t)b * S_ + s) * H_ + h) * DH + d], acc);
    ob[tid] = acc;
    __syncthreads();
    if (tid < DH) {
        float tot = 0.f;
        #pragma unroll
        for (int k = 0; k < 8; k++) tot += ob[d + 64 * k];
        O[(((size_t)b * S_) * H_ + h) * DH + tid] = __float2half_rn(tot / gs);
    }
}

// ================= host side =================
static void gemm_h(const __half* A, const __half* Bw, const float* bias, void* C,
                   int M, int N, int K, float alpha, bool relu, bool hout)
{
    dim3 grid(N / GTN, M / GTM);
    if (relu) {
        if (hout) gemm_h_kernel<true, true ><<<grid, 512, GEMM_SMEM>>>(A, Bw, bias, C, M, N, K, alpha);
        else      gemm_h_kernel<true, false><<<grid, 512, GEMM_SMEM>>>(A, Bw, bias, C, M, N, K, alpha);
    } else {
        if (hout) gemm_h_kernel<false, true ><<<grid, 512, GEMM_SMEM>>>(A, Bw, bias, C, M, N, K, alpha);
        else      gemm_h_kernel<false, false><<<grid, 512, GEMM_SMEM>>>(A, Bw, bias, C, M, N, K, alpha);
    }
}

static void cvt(const float* s, __half* d, size_t n) {
    int blocks = (int)((n / 4 + 255) / 256);
    cvt_f2h_kernel<<<blocks, 256>>>(s, d, (int)n);
}

extern "C" void kernel_launch(void* const* d_in, const int* in_sizes, int n_in,
                              void* d_out, int out_size)
{
    const int* call = (const int*)d_in[0];

    int e = 9;
    for (int i = 0; i < n_in; i++) {
        if (in_sizes[i] == V_ * D_) { e = i; break; }
    }
    const float* emb   = (const float*)d_in[e + 0];
    const float* Wq    = (const float*)d_in[e + 1];
    const float* bq    = (const float*)d_in[e + 2];
    const float* Wk    = (const float*)d_in[e + 3];
    const float* bk    = (const float*)d_in[e + 4];
    const float* Wv    = (const float*)d_in[e + 5];
    const float* bv    = (const float*)d_in[e + 6];
    const float* Wo    = (const float*)d_in[e + 7];
    const float* bo    = (const float*)d_in[e + 8];
    const float* W1    = (const float*)d_in[e + 9];
    const float* b1    = (const float*)d_in[e + 10];
    const float* W2    = (const float*)d_in[e + 11];
    const float* b2    = (const float*)d_in[e + 12];
    const float* g1    = (const float*)d_in[e + 13];
    const float* beta1 = (const float*)d_in[e + 14];
    const float* g2    = (const float*)d_in[e + 15];
    const float* beta2 = (const float*)d_in[e + 16];
    const float* gf    = (const float*)d_in[e + 17];
    const float* betaf = (const float*)d_in[e + 18];
    const float* Wc    = (const float*)d_in[e + 19];
    const float* bc    = (const float*)d_in[e + 20];
    float* out = (float*)d_out;

    float *X, *Qb, *Kb, *Vb, *T1;
    __half *XH, *ATTH, *T1H, *HH, *WHq, *WHk, *WHv, *WHo, *WH1, *WH2, *WHc;
    cudaGetSymbolAddress((void**)&X,    g_X);
    cudaGetSymbolAddress((void**)&XH,   g_XH);
    cudaGetSymbolAddress((void**)&Qb,   g_Q);
    cudaGetSymbolAddress((void**)&Kb,   g_K);
    cudaGetSymbolAddress((void**)&Vb,   g_V);
    cudaGetSymbolAddress((void**)&ATTH, g_ATTH);
    cudaGetSymbolAddress((void**)&T1,   g_T1);
    cudaGetSymbolAddress((void**)&T1H,  g_T1H);
    cudaGetSymbolAddress((void**)&HH,   g_HH);
    cudaGetSymbolAddress((void**)&WHq,  g_WHq);
    cudaGetSymbolAddress((void**)&WHk,  g_WHk);
    cudaGetSymbolAddress((void**)&WHv,  g_WHv);
    cudaGetSymbolAddress((void**)&WHo,  g_WHo);
    cudaGetSymbolAddress((void**)&WH1,  g_WH1);
    cudaGetSymbolAddress((void**)&WH2,  g_WH2);
    cudaGetSymbolAddress((void**)&WHc,  g_WHc);

    cudaFuncSetAttribute(gemm_h_kernel<false, false>,
                         cudaFuncAttributeMaxDynamicSharedMemorySize, GEMM_SMEM);
    cudaFuncSetAttribute(gemm_h_kernel<false, true>,
                         cudaFuncAttributeMaxDynamicSharedMemorySize, GEMM_SMEM);
    cudaFuncSetAttribute(gemm_h_kernel<true, false>,
                         cudaFuncAttributeMaxDynamicSharedMemorySize, GEMM_SMEM);
    cudaFuncSetAttribute(gemm_h_kernel<true, true>,
                         cudaFuncAttributeMaxDynamicSharedMemorySize, GEMM_SMEM);
    cudaFuncSetAttribute(band_attn_kernel,
                         cudaFuncAttributeMaxDynamicSharedMemorySize, SMEM_BAND);

    // weights -> fp16 (RNE)
    cvt(Wq, WHq, (size_t)L_ * D_ * D_);
    cvt(Wk, WHk, (size_t)L_ * D_ * D_);
    cvt(Wv, WHv, (size_t)L_ * D_ * D_);
    cvt(Wo, WHo, (size_t)L_ * D_ * D_);
    cvt(W1, WH1, (size_t)L_ * FF_ * D_);
    cvt(W2, WH2, (size_t)L_ * FF_ * D_);
    cvt(Wc, WHc, (size_t)V_ * D_);

    embed_kernel<<<BSi, 256>>>(call, emb, X, XH);

    const dim3 gAttn(NB, H_, B_);
    const dim3 gGlob(H_, B_);
    const size_t DD = (size_t)D_ * D_;
    const size_t FD = (size_t)FF_ * D_;

    for (int l = 0; l < L_; l++) {
        gemm_h(XH, WHq + l * DD, bq + l * D_, Qb, BSi, D_, D_, 0.125f, false, false);
        gemm_h(XH, WHk + l * DD, bk + l * D_, Kb, BSi, D_, D_, 1.f, false, false);
        gemm_h(XH, WHv + l * DD, bv + l * D_, Vb, BSi, D_, D_, 1.f, false, false);

        band_attn_kernel<<<gAttn, 128, SMEM_BAND>>>(Qb, Kb, Vb, ATTH);
        global_attn_kernel<<<gGlob, 512>>>(Qb, Kb, Vb, ATTH);

        gemm_h(ATTH, WHo + l * DD, bo + l * D_, T1, BSi, D_, D_, 1.f, false, false);
        add_ln_kernel<<<BSi, 256>>>(X, T1, g1 + l * D_, beta1 + l * D_, X, XH);

        gemm_h(XH, WH1 + l * FD, b1 + l * FF_, HH, BSi, FF_, D_, 1.f, true, true);
        gemm_h(HH, WH2 + l * FD, b2 + l * D_, T1, BSi, D_, FF_, 1.f, false, false);
        add_ln_kernel<<<BSi, 256>>>(X, T1, g2 + l * D_, beta2 + l * D_, X, XH);
    }

    add_ln_kernel<<<BSi, 256>>>(X, nullptr, gf, betaf, nullptr, T1H);
    gemm_h(T1H, WHc, bc, out, BSi, V_, D_, 1.f, false, false);
}

// round 9
// speedup vs baseline: 1.0681x; 1.0278x over previous
#include <cuda_runtime.h>
#include <cuda_fp16.h>
#include <math.h>
#include <stdint.h>

// ---------------- problem constants ----------------
constexpr int B_  = 8;
constexpr int S_  = 4096;
constexpr int D_  = 768;
constexpr int H_  = 12;
constexpr int Wd  = 128;     // window
constexpr int L_  = 2;
constexpr int V_  = 512;
constexpr int FF_ = 3072;
constexpr int DH  = 64;      // D_/H_
constexpr int NB  = S_ / Wd; // 32
constexpr int BSi = B_ * S_; // 32768

// ---------------- scratch (device globals; no allocation allowed) ----------------
__device__ float  g_X  [(size_t)BSi * D_];   // fp32 residual stream
__device__ __half g_XH [(size_t)BSi * D_];   // half copy (GEMM A input)
__device__ float  g_Q  [(size_t)BSi * D_];
__device__ float  g_K  [(size_t)BSi * D_];
__device__ float  g_V  [(size_t)BSi * D_];
__device__ __half g_ATTH[(size_t)BSi * D_];  // attention out (half, feeds Wo)
__device__ float  g_T1 [(size_t)BSi * D_];
__device__ __half g_T1H[(size_t)BSi * D_];
__device__ __half g_HH [(size_t)BSi * FF_];  // FF intermediate (half)
// half weights
__device__ __half g_WQKV[(size_t)L_ * 3 * D_ * D_]; // [L][2304][768]
__device__ float  g_bQKV[(size_t)L_ * 3 * D_];      // combined bias
__device__ __half g_WHo[(size_t)L_ * D_ * D_];
__device__ __half g_WH1[(size_t)L_ * FF_ * D_];
__device__ __half g_WH2[(size_t)L_ * FF_ * D_];
__device__ __half g_WHc[(size_t)V_ * D_];

// ---------------- helpers ----------------
__device__ __forceinline__ uint32_t smem_u32(const void* p) {
    uint32_t a;
    asm("{ .reg .u64 t; cvta.to.shared.u64 t, %1; cvt.u32.u64 %0, t; }" : "=r"(a) : "l"(p));
    return a;
}
__device__ __forceinline__ float warp_sum(float v) {
    #pragma unroll
    for (int o = 16; o > 0; o >>= 1) v += __shfl_xor_sync(0xffffffffu, v, o);
    return v;
}
__device__ __forceinline__ float warp_max(float v) {
    #pragma unroll
    for (int o = 16; o > 0; o >>= 1) v = fmaxf(v, __shfl_xor_sync(0xffffffffu, v, o));
    return v;
}
__device__ __forceinline__ void mma_f16(float* c, const uint32_t* a, const uint32_t* b) {
    asm volatile(
        "mma.sync.aligned.m16n8k16.row.col.f32.f16.f16.f32 "
        "{%0,%1,%2,%3}, {%4,%5,%6,%7}, {%8,%9}, {%0,%1,%2,%3};"
        : "+f"(c[0]), "+f"(c[1]), "+f"(c[2]), "+f"(c[3])
        : "r"(a[0]), "r"(a[1]), "r"(a[2]), "r"(a[3]), "r"(b[0]), "r"(b[1]));
}
#define CP_ASYNC16(dst, src) \
    asm volatile("cp.async.cg.shared.global [%0], [%1], 16;" :: "r"(dst), "l"(src))
#define CP_COMMIT() asm volatile("cp.async.commit_group;" ::: "memory")

typedef unsigned long long u64t;
#define PACK2(d, lo, hi) asm("mov.b64 %0, {%1,%2};" : "=l"(d) : "f"(lo), "f"(hi))
#define UNPACK2(lo, hi, s) asm("mov.b64 {%0,%1}, %2;" : "=f"(lo), "=f"(hi) : "l"(s))
#define FFMA2(d, a, b) asm("fma.rn.f32x2 %0, %1, %2, %0;" : "+l"(d) : "l"(a), "l"(b))
#define FMUL2(d, a, b) asm("mul.rn.f32x2 %0, %1, %2;" : "=l"(d) : "l"(a), "l"(b))

// ================= fp16 tensor-core GEMM (round-6 core) =================
constexpr int GTM = 128, GTN = 256, GKC = 32, GSTG = 3;
constexpr int HSTRIDE = 40;                       // halves per smem row
constexpr int A_H = GTM * HSTRIDE;                // 5120 halves
constexpr int B_H = GTN * HSTRIDE;                // 10240 halves
constexpr int STAGE_H = A_H + B_H;                // 15360 halves
constexpr int GEMM_SMEM = GSTG * STAGE_H * 2;     // 92160 bytes

// shared mainloop pieces as macros over local names
#define GEMM_PROLOGUE() \
    extern __shared__ __half smh[]; \
    const int tid = threadIdx.x, wid = tid >> 5, lane = tid & 31; \
    const int g = lane >> 2, tig = lane & 3; \
    const int wm = (wid & 1) * 64; \
    const int wn = (wid >> 1) * 64; \
    const int tile_m = blockIdx.y * GTM, tile_n = blockIdx.x * GTN; \
    float c[4][8][4]; \
    _Pragma("unroll") \
    for (int i = 0; i < 4; i++) \
        _Pragma("unroll") \
        for (int j = 0; j < 8; j++) \
            _Pragma("unroll") \
            for (int r = 0; r < 4; r++) c[i][j][r] = 0.f; \
    const int arow = tid >> 2, ac = tid & 3; \
    auto loadStage = [&](int st, int k0) { \
        __half* base = smh + st * STAGE_H; \
        const __half* Ag = A + (size_t)(tile_m + arow) * K + k0 + ac * 8; \
        uint32_t da = smem_u32(base + arow * HSTRIDE + ac * 8); \
        CP_ASYNC16(da, Ag); \
        CP_ASYNC16(da + 64 * HSTRIDE * 2, Ag + (size_t)64 * K); \
        const __half* Bg = Bw + (size_t)(tile_n + arow) * K + k0 + ac * 8; \
        uint32_t db = smem_u32(base + A_H + arow * HSTRIDE + ac * 8); \
        _Pragma("unroll") \
        for (int i = 0; i < 4; i++) \
            CP_ASYNC16(db + i * 64 * HSTRIDE * 2, Bg + (size_t)(i * 64) * K); \
    }; \
    auto compute = [&](int st) { \
        const uint32_t* Aw = (const uint32_t*)(smh + st * STAGE_H); \
        const uint32_t* Bv = (const uint32_t*)(smh + st * STAGE_H + A_H); \
        _Pragma("unroll") \
        for (int kk = 0; kk < 2; kk++) { \
            uint32_t af[4][4], bf[8][2]; \
            _Pragma("unroll") \
            for (int mm = 0; mm < 4; mm++) { \
                const uint32_t* p = Aw + (wm + mm * 16 + g) * 20 + kk * 8 + tig; \
                af[mm][0] = p[0]; \
                af[mm][1] = p[8 * 20]; \
                af[mm][2] = p[4]; \
                af[mm][3] = p[8 * 20 + 4]; \
            } \
            _Pragma("unroll") \
            for (int nn = 0; nn < 8; nn++) { \
                const uint32_t* p = Bv + (wn + nn * 8 + g) * 20 + kk * 8 + tig; \
                bf[nn][0] = p[0]; \
                bf[nn][1] = p[4]; \
            } \
            _Pragma("unroll") \
            for (int mm = 0; mm < 4; mm++) \
                _Pragma("unroll") \
                for (int nn = 0; nn < 8; nn++) \
                    mma_f16(c[mm][nn], af[mm], bf[nn]); \
        } \
    }; \
    const int NK = K / GKC; \
    loadStage(0, 0);   CP_COMMIT(); \
    loadStage(1, GKC); CP_COMMIT(); \
    for (int ks = 0; ks < NK; ks++) { \
        if (ks + 1 == NK) { asm volatile("cp.async.wait_group 0;" ::: "memory"); } \
        else              { asm volatile("cp.async.wait_group 1;" ::: "memory"); } \
        __syncthreads(); \
        compute(ks % 3); \
        if (ks + 2 < NK) { loadStage((ks + 2) % 3, (ks + 2) * GKC); CP_COMMIT(); } \
    }

template<bool RELU, bool HOUT>
__global__ void __launch_bounds__(256) gemm_h_kernel(
    const __half* __restrict__ A, const __half* __restrict__ Bw,
    const float* __restrict__ bias, void* __restrict__ Cv,
    int M, int N, int K, float alpha)
{
    GEMM_PROLOGUE();

    #pragma unroll
    for (int mm = 0; mm < 4; mm++) {
        const int r0 = tile_m + wm + mm * 16 + g;
        #pragma unroll
        for (int nn = 0; nn < 8; nn++) {
            const int col = tile_n + wn + nn * 8 + 2 * tig;
            const float b0 = bias[col], b1 = bias[col + 1];
            float v0 = (c[mm][nn][0] + b0) * alpha;
            float v1 = (c[mm][nn][1] + b1) * alpha;
            float v2 = (c[mm][nn][2] + b0) * alpha;
            float v3 = (c[mm][nn][3] + b1) * alpha;
            if (RELU) {
                v0 = fmaxf(v0, 0.f); v1 = fmaxf(v1, 0.f);
                v2 = fmaxf(v2, 0.f); v3 = fmaxf(v3, 0.f);
            }
            if (HOUT) {
                __half* C = (__half*)Cv;
                *(__half2*)(C + (size_t)r0 * N + col)       = __floats2half2_rn(v0, v1);
                *(__half2*)(C + (size_t)(r0 + 8) * N + col) = __floats2half2_rn(v2, v3);
            } else {
                float* C = (float*)Cv;
                *(float2*)(C + (size_t)r0 * N + col)       = make_float2(v0, v1);
                *(float2*)(C + (size_t)(r0 + 8) * N + col) = make_float2(v2, v3);
            }
        }
    }
}

// fused QKV GEMM: N = 2304, epilogue routes per 768-column region.
__global__ void __launch_bounds__(256) gemm_qkv_kernel(
    const __half* __restrict__ A, const __half* __restrict__ Bw,
    const float* __restrict__ bias,
    float* __restrict__ Qf, float* __restrict__ Kf, float* __restrict__ Vf,
    int M, int K)
{
    GEMM_PROLOGUE();

    const int region = tile_n / D_;                 // 0=Q, 1=K, 2=V
    const float alf = (region == 0) ? 0.125f : 1.0f;
    float* Cd = (region == 0) ? Qf : ((region == 1) ? Kf : Vf);
    const int ncol0 = tile_n - region * D_;

    #pragma unroll
    for (int mm = 0; mm < 4; mm++) {
        const int r0 = tile_m + wm + mm * 16 + g;
        #pragma unroll
        for (int nn = 0; nn < 8; nn++) {
            const int coln = wn + nn * 8 + 2 * tig;     // within tile
            const int colg = tile_n + coln;              // global (bias)
            const float b0 = bias[colg], b1 = bias[colg + 1];
            float v0 = (c[mm][nn][0] + b0) * alf;
            float v1 = (c[mm][nn][1] + b1) * alf;
            float v2 = (c[mm][nn][2] + b0) * alf;
            float v3 = (c[mm][nn][3] + b1) * alf;
            *(float2*)(Cd + (size_t)r0 * D_ + ncol0 + coln)       = make_float2(v0, v1);
            *(float2*)(Cd + (size_t)(r0 + 8) * D_ + ncol0 + coln) = make_float2(v2, v3);
        }
    }
}

// ================= fused weight conversion (single launch) =================
constexpr size_t DDq_  = (size_t)L_ * D_ * D_ / 4;   // quads per D*D weight set
constexpr size_t FDq_  = (size_t)L_ * FF_ * D_ / 4;
constexpr size_t CQ_   = (size_t)V_ * D_ / 4;
constexpr size_t BQ_   = (size_t)L_ * 3 * D_ / 4;    // bias quads
constexpr size_t CVT_E0 = 3 * DDq_;                  // Wq,Wk,Wv -> WQKV
constexpr size_t CVT_E1 = CVT_E0 + DDq_;             // Wo
constexpr size_t CVT_E2 = CVT_E1 + FDq_;             // W1
constexpr size_t CVT_E3 = CVT_E2 + FDq_;             // W2
constexpr size_t CVT_E4 = CVT_E3 + CQ_;              // Wc
constexpr size_t CVT_E5 = CVT_E4 + BQ_;              // bias pack
constexpr int CVT_BLOCKS = (int)((CVT_E5 + 255) / 256);

__device__ __forceinline__ void st_h4(__half* d, float4 f) {
    *(__half2*)(d)     = __floats2half2_rn(f.x, f.y);
    *(__half2*)(d + 2) = __floats2half2_rn(f.z, f.w);
}

__global__ void cvt_all_kernel(
    const float* __restrict__ Wq, const float* __restrict__ Wk,
    const float* __restrict__ Wv, const float* __restrict__ Wo,
    const float* __restrict__ W1, const float* __restrict__ W2,
    const float* __restrict__ Wc,
    const float* __restrict__ bq, const float* __restrict__ bk,
    const float* __restrict__ bv,
    __half* __restrict__ WQKV, __half* __restrict__ WHo,
    __half* __restrict__ WH1, __half* __restrict__ WH2,
    __half* __restrict__ WHc, float* __restrict__ bQKV)
{
    const size_t t = (size_t)blockIdx.x * 256 + threadIdx.x;
    constexpr size_t DD = (size_t)D_ * D_;
    if (t < CVT_E0) {
        const int s = (int)(t / DDq_);
        const size_t i = (t - (size_t)s * DDq_) * 4;
        const float* src = (s == 0) ? Wq : ((s == 1) ? Wk : Wv);
        const size_t l = i / DD, rem = i - l * DD;
        float4 f = *(const float4*)(src + i);
        st_h4(WQKV + l * (3 * DD) + (size_t)s * DD + rem, f);
    } else if (t < CVT_E1) {
        const size_t i = (t - CVT_E0) * 4;
        st_h4(WHo + i, *(const float4*)(Wo + i));
    } else if (t < CVT_E2) {
        const size_t i = (t - CVT_E1) * 4;
        st_h4(WH1 + i, *(const float4*)(W1 + i));
    } else if (t < CVT_E3) {
        const size_t i = (t - CVT_E2) * 4;
        st_h4(WH2 + i, *(const float4*)(W2 + i));
    } else if (t < CVT_E4) {
        const size_t i = (t - CVT_E3) * 4;
        st_h4(WHc + i, *(const float4*)(Wc + i));
    } else if (t < CVT_E5) {
        const size_t i = (t - CVT_E4) * 4;
        const size_t l = i / (3 * D_);
        const int j = (int)(i - l * (3 * D_));
        const float* src = (j < D_) ? (bq + l * D_ + j)
                        : (j < 2 * D_) ? (bk + l * D_ + (j - D_))
                                       : (bv + l * D_ + (j - 2 * D_));
        *(float4*)(bQKV + i) = *(const float4*)src;
    }
}

// ================= embedding gather (fp32 + fp16 copies) =================
__global__ void embed_kernel(const int* __restrict__ call,
                             const float* __restrict__ emb,
                             float* __restrict__ X, __half* __restrict__ XH)
{
    size_t row = blockIdx.x;
    int c = call[row];
    const float* src = emb + (size_t)c * D_;
    float*  dst  = X  + row * D_;
    __half* dsth = XH + row * D_;
    for (int d = threadIdx.x; d < D_; d += blockDim.x) {
        float v = src[d];
        dst[d]  = v;
        dsth[d] = __float2half_rn(v);
    }
}

// ================= fused residual add + LayerNorm (fp32 + optional fp16 out) ====
__global__ void __launch_bounds__(256) add_ln_kernel(
    const float* __restrict__ x, const float* __restrict__ a,
    const float* __restrict__ g, const float* __restrict__ beta,
    float* __restrict__ out, __half* __restrict__ outh)
{
    __shared__ float red[8];
    const int row = blockIdx.x;
    const int tid = threadIdx.x;
    const int lane = tid & 31, wid = tid >> 5;
    const float* xr = x + (size_t)row * D_;
    const float* ar = a ? (a + (size_t)row * D_) : nullptr;
    float v[3];
    float s = 0.f;
    #pragma unroll
    for (int i = 0; i < 3; i++) {
        int c = tid + i * 256;
        float val = xr[c];
        if (ar) val += ar[c];
        v[i] = val;
        s += val;
    }
    s = warp_sum(s);
    if (lane == 0) red[wid] = s;
    __syncthreads();
    float tot = 0.f;
    #pragma unroll
    for (int w = 0; w < 8; w++) tot += red[w];
    float mean = tot * (1.f / (float)D_);
    float s2 = 0.f;
    #pragma unroll
    for (int i = 0; i < 3; i++) { float d = v[i] - mean; s2 += d * d; }
    s2 = warp_sum(s2);
    __syncthreads();
    if (lane == 0) red[wid] = s2;
    __syncthreads();
    float tot2 = 0.f;
    #pragma unroll
    for (int w = 0; w < 8; w++) tot2 += red[w];
    float rs = rsqrtf(tot2 * (1.f / (float)D_) + 1e-5f);
    float*  orow = out  ? out  + (size_t)row * D_ : nullptr;
    __half* hrow = outh ? outh + (size_t)row * D_ : nullptr;
    #pragma unroll
    for (int i = 0; i < 3; i++) {
        int c = tid + i * 256;
        float val = (v[i] - mean) * rs * g[c] + beta[c];
        if (orow) orow[c] = val;
        if (hrow) hrow[c] = __float2half_rn(val);
    }
}

// ================= banded attention: chunked smem, warp-uniform iteration ======
constexpr int BCH      = 128;  // keys per chunk
constexpr int BSTRIDE  = 68;   // floats per smem row (16B aligned, padded)
constexpr int SMEM_BAND = 2 * BCH * BSTRIDE * (int)sizeof(float); // 69632

__global__ void __launch_bounds__(128) band_attn_kernel(
    const float* __restrict__ Qf, const float* __restrict__ Kf,
    const float* __restrict__ Vf, __half* __restrict__ O)
{
    extern __shared__ float smb[];
    float* Ks = smb;
    float* Vs = smb + BCH * BSTRIDE;

    const int n = blockIdx.x, h = blockIdx.y, b = blockIdx.z;
    const int i = threadIdx.x;
    const int qpos = n * Wd + i;

    u64t q2[32], acc2[32];
    {
        const ulonglong2* qp = (const ulonglong2*)(Qf + (((size_t)b * S_ + qpos) * H_ + h) * DH);
        #pragma unroll
        for (int c = 0; c < 16; c++) { ulonglong2 t = qp[c]; q2[2*c] = t.x; q2[2*c+1] = t.y; }
    }
    #pragma unroll
    for (int k = 0; k < 32; k++) acc2[k] = 0ull;
    float m = -1e30f, ssum = 0.f;

    // ---- global key 0 first (direct LDG, all lanes same row -> broadcast) ----
    {
        const ulonglong2* kr = (const ulonglong2*)(Kf + ((size_t)b * S_ * H_ + h) * DH);
        const ulonglong2* vr = (const ulonglong2*)(Vf + ((size_t)b * S_ * H_ + h) * DH);
        u64t s2 = 0ull;
        #pragma unroll
        for (int c = 0; c < 16; c++) {
            ulonglong2 kv = kr[c];
            FFMA2(s2, q2[2*c], kv.x);
            FFMA2(s2, q2[2*c+1], kv.y);
        }
        float sa, sb;
        UNPACK2(sa, sb, s2);
        float s = sa + sb;          // no bias on the global column
        m = s; ssum = 1.f;          // first key: p = 1
        #pragma unroll
        for (int c = 0; c < 16; c++) {
            ulonglong2 vv = vr[c];
            float lo, hi;
            UNPACK2(lo, hi, vv.x); PACK2(acc2[2*c],   lo, hi);
            UNPACK2(lo, hi, vv.y); PACK2(acc2[2*c+1], lo, hi);
        }
    }

    const int base = n * Wd - Wd;
    int lo = i, hi = i + 2 * Wd;
    if (n == 0 && lo < Wd) lo = Wd;
    if (hi > 383) hi = 383;
    if (n == NB - 1 && hi > 255) hi = 255;

    for (int c = 0; c < 3; c++) {
        if (n == 0 && c == 0) continue;
        if (n == NB - 1 && c == 2) continue;
        const int clo = c * BCH;
        __syncthreads();
        for (int t = i; t < BCH * 16; t += 128) {
            int row = t >> 4, col = t & 15;
            size_t gb = (((size_t)b * S_ + (base + clo + row)) * H_ + h) * DH + col * 4;
            *(float4*)(Ks + row * BSTRIDE + col * 4) = *(const float4*)(Kf + gb);
            *(float4*)(Vs + row * BSTRIDE + col * 4) = *(const float4*)(Vf + gb);
        }
        __syncthreads();

        int llo = lo > clo ? lo : clo;
        int lhi = hi < clo + BCH - 1 ? hi : clo + BCH - 1;
        int wlo = __shfl_sync(0xffffffffu, llo, 0);
        int whi = __shfl_sync(0xffffffffu, lhi, 31);
        for (int jj = wlo; jj <= whi; jj++) {
            if (jj < llo || jj > lhi) continue;
            const int row = jj - clo;
            const int pos = base + jj;
            const ulonglong2* kr = (const ulonglong2*)(Ks + row * BSTRIDE);
            u64t s2 = 0ull;
            #pragma unroll
            for (int cc = 0; cc < 16; cc++) {
                ulonglong2 kv = kr[cc];
                FFMA2(s2, q2[2*cc], kv.x);
                FFMA2(s2, q2[2*cc+1], kv.y);
            }
            float sa, sb;
            UNPACK2(sa, sb, s2);
            float s = sa + sb + ((pos == 0) ? -10000.f : 0.f);
            if (s > m) {
                float corr = __expf(m - s);
                u64t cc2; PACK2(cc2, corr, corr);
                ssum *= corr;
                #pragma unroll
                for (int k = 0; k < 32; k++) FMUL2(acc2[k], acc2[k], cc2);
                m = s;
            }
            float p = __expf(s - m);
            ssum += p;
            u64t pp; PACK2(pp, p, p);
            const ulonglong2* vr = (const ulonglong2*)(Vs + row * BSTRIDE);
            #pragma unroll
            for (int cc = 0; cc < 16; cc++) {
                ulonglong2 vv = vr[cc];
                FFMA2(acc2[2*cc],   pp, vv.x);
                FFMA2(acc2[2*cc+1], pp, vv.y);
            }
        }
    }

    float inv = 1.f / ssum;
    __half* op = O + (((size_t)b * S_ + qpos) * H_ + h) * DH;
    #pragma unroll
    for (int c = 0; c < 32; c++) {
        float lo2, hi2;
        UNPACK2(lo2, hi2, acc2[c]);
        *(__half2*)(op + 2 * c) = __floats2half2_rn(lo2 * inv, hi2 * inv);
    }
}

// ================= full attention for the global query (s = 0) =================
__global__ void __launch_bounds__(512) global_attn_kernel(
    const float* __restrict__ Q, const float* __restrict__ Kt,
    const float* __restrict__ Vt, __half* __restrict__ O)
{
    __shared__ float qs[DH];
    __shared__ float sc[S_];
    __shared__ float red[16];
    __shared__ float ob[512];
    const int h = blockIdx.x, b = blockIdx.y;
    const int tid = threadIdx.x;
    const int lane = tid & 31, wid = tid >> 5;
    if (tid < DH) qs[tid] = Q[(((size_t)b * S_) * H_ + h) * DH + tid];
    __syncthreads();
    float lm = -1e30f;
    for (int s = tid; s < S_; s += 512) {
        const float* kp = Kt + (((size_t)b * S_ + s) * H_ + h) * DH;
        float d0 = 0.f, d1 = 0.f, d2 = 0.f, d3 = 0.f;
        #pragma unroll
        for (int c = 0; c < 16; c++) {
            d0 = fmaf(qs[c*4+0], kp[c*4+0], d0); d1 = fmaf(qs[c*4+1], kp[c*4+1], d1);
            d2 = fmaf(qs[c*4+2], kp[c*4+2], d2); d3 = fmaf(qs[c*4+3], kp[c*4+3], d3);
        }
        float sv = (d0 + d1) + (d2 + d3);
        sc[s] = sv;
        lm = fmaxf(lm, sv);
    }
    lm = warp_max(lm);
    if (lane == 0) red[wid] = lm;
    __syncthreads();
    float gm = -1e30f;
    #pragma unroll
    for (int w = 0; w < 16; w++) gm = fmaxf(gm, red[w]);
    float ls = 0.f;
    for (int s = tid; s < S_; s += 512) {
        float p = __expf(sc[s] - gm);
        sc[s] = p;
        ls += p;
    }
    ls = warp_sum(ls);
    __syncthreads();
    if (lane == 0) red[wid] = ls;
    __syncthreads();
    float gs = 0.f;
    #pragma unroll
    for (int w = 0; w < 16; w++) gs += red[w];
    const int d = tid & 63, seg = tid >> 6;
    float acc = 0.f;
    const int s0 = seg * (S_ / 8), s1 = s0 + (S_ / 8);
    for (int s = s0; s < s1; s++)
        acc = fmaf(sc[s], Vt[(((size_t)b * S_ + s) * H_ + h) * DH + d], acc);
    ob[tid] = acc;
    __syncthreads();
    if (tid < DH) {
        float tot = 0.f;
        #pragma unroll
        for (int k = 0; k < 8; k++) tot += ob[d + 64 * k];
        O[(((size_t)b * S_) * H_ + h) * DH + tid] = __float2half_rn(tot / gs);
    }
}

// ================= host side =================
static void gemm_h(const __half* A, const __half* Bw, const float* bias, void* C,
                   int M, int N, int K, float alpha, bool relu, bool hout)
{
    dim3 grid(N / GTN, M / GTM);
    if (relu) {
        if (hout) gemm_h_kernel<true, true ><<<grid, 256, GEMM_SMEM>>>(A, Bw, bias, C, M, N, K, alpha);
        else      gemm_h_kernel<true, false><<<grid, 256, GEMM_SMEM>>>(A, Bw, bias, C, M, N, K, alpha);
    } else {
        if (hout) gemm_h_kernel<false, true ><<<grid, 256, GEMM_SMEM>>>(A, Bw, bias, C, M, N, K, alpha);
        else      gemm_h_kernel<false, false><<<grid, 256, GEMM_SMEM>>>(A, Bw, bias, C, M, N, K, alpha);
    }
}

extern "C" void kernel_launch(void* const* d_in, const int* in_sizes, int n_in,
                              void* d_out, int out_size)
{
    const int* call = (const int*)d_in[0];

    int e = 9;
    for (int i = 0; i < n_in; i++) {
        if (in_sizes[i] == V_ * D_) { e = i; break; }
    }
    const float* emb   = (const float*)d_in[e + 0];
    const float* Wq    = (const float*)d_in[e + 1];
    const float* bq    = (const float*)d_in[e + 2];
    const float* Wk    = (const float*)d_in[e + 3];
    const float* bk    = (const float*)d_in[e + 4];
    const float* Wv    = (const float*)d_in[e + 5];
    const float* bv    = (const float*)d_in[e + 6];
    const float* Wo    = (const float*)d_in[e + 7];
    const float* bo    = (const float*)d_in[e + 8];
    const float* W1    = (const float*)d_in[e + 9];
    const float* b1    = (const float*)d_in[e + 10];
    const float* W2    = (const float*)d_in[e + 11];
    const float* b2    = (const float*)d_in[e + 12];
    const float* g1    = (const float*)d_in[e + 13];
    const float* beta1 = (const float*)d_in[e + 14];
    const float* g2    = (const float*)d_in[e + 15];
    const float* beta2 = (const float*)d_in[e + 16];
    const float* gf    = (const float*)d_in[e + 17];
    const float* betaf = (const float*)d_in[e + 18];
    const float* Wc    = (const float*)d_in[e + 19];
    const float* bc    = (const float*)d_in[e + 20];
    float* out = (float*)d_out;

    float *X, *Qb, *Kb, *Vb, *T1, *bQKV;
    __half *XH, *ATTH, *T1H, *HH, *WQKV, *WHo, *WH1, *WH2, *WHc;
    cudaGetSymbolAddress((void**)&X,    g_X);
    cudaGetSymbolAddress((void**)&XH,   g_XH);
    cudaGetSymbolAddress((void**)&Qb,   g_Q);
    cudaGetSymbolAddress((void**)&Kb,   g_K);
    cudaGetSymbolAddress((void**)&Vb,   g_V);
    cudaGetSymbolAddress((void**)&ATTH, g_ATTH);
    cudaGetSymbolAddress((void**)&T1,   g_T1);
    cudaGetSymbolAddress((void**)&T1H,  g_T1H);
    cudaGetSymbolAddress((void**)&HH,   g_HH);
    cudaGetSymbolAddress((void**)&WQKV, g_WQKV);
    cudaGetSymbolAddress((void**)&bQKV, g_bQKV);
    cudaGetSymbolAddress((void**)&WHo,  g_WHo);
    cudaGetSymbolAddress((void**)&WH1,  g_WH1);
    cudaGetSymbolAddress((void**)&WH2,  g_WH2);
    cudaGetSymbolAddress((void**)&WHc,  g_WHc);

    cudaFuncSetAttribute(gemm_h_kernel<false, false>,
                         cudaFuncAttributeMaxDynamicSharedMemorySize, GEMM_SMEM);
    cudaFuncSetAttribute(gemm_h_kernel<false, true>,
                         cudaFuncAttributeMaxDynamicSharedMemorySize, GEMM_SMEM);
    cudaFuncSetAttribute(gemm_h_kernel<true, false>,
                         cudaFuncAttributeMaxDynamicSharedMemorySize, GEMM_SMEM);
    cudaFuncSetAttribute(gemm_h_kernel<true, true>,
                         cudaFuncAttributeMaxDynamicSharedMemorySize, GEMM_SMEM);
    cudaFuncSetAttribute(gemm_qkv_kernel,
                         cudaFuncAttributeMaxDynamicSharedMemorySize, GEMM_SMEM);
    cudaFuncSetAttribute(band_attn_kernel,
                         cudaFuncAttributeMaxDynamicSharedMemorySize, SMEM_BAND);

    // launch 1: all weight conversions + QKV pack + bias pack
    cvt_all_kernel<<<CVT_BLOCKS, 256>>>(Wq, Wk, Wv, Wo, W1, W2, Wc, bq, bk, bv,
                                        WQKV, WHo, WH1, WH2, WHc, bQKV);
    // launch 2: embedding
    embed_kernel<<<BSi, 256>>>(call, emb, X, XH);

    const dim3 gAttn(NB, H_, B_);
    const dim3 gGlob(H_, B_);
    const dim3 gQKV(3 * D_ / GTN, BSi / GTM);   // 9 x 256
    const size_t DD = (size_t)D_ * D_;
    const size_t FD = (size_t)FF_ * D_;

    for (int l = 0; l < L_; l++) {
        // fused Q/K/V projection (launch 3 on first layer)
        gemm_qkv_kernel<<<gQKV, 256, GEMM_SMEM>>>(
            XH, WQKV + (size_t)l * 3 * DD, bQKV + (size_t)l * 3 * D_,
            Qb, Kb, Vb, BSi, D_);

        band_attn_kernel<<<gAttn, 128, SMEM_BAND>>>(Qb, Kb, Vb, ATTH);   // 4
        global_attn_kernel<<<gGlob, 512>>>(Qb, Kb, Vb, ATTH);            // 5

        gemm_h(ATTH, WHo + l * DD, bo + l * D_, T1, BSi, D_, D_, 1.f, false, false); // 6 <- ncu
        add_ln_kernel<<<BSi, 256>>>(X, T1, g1 + l * D_, beta1 + l * D_, X, XH);

        gemm_h(XH, WH1 + l * FD, b1 + l * FF_, HH, BSi, FF_, D_, 1.f, true, true);
        gemm_h(HH, WH2 + l * FD, b2 + l * D_, T1, BSi, D_, FF_, 1.f, false, false);
        add_ln_kernel<<<BSi, 256>>>(X, T1, g2 + l * D_, beta2 + l * D_, X, XH);
    }

    add_ln_kernel<<<BSi, 256>>>(X, nullptr, gf, betaf, nullptr, T1H);
    gemm_h(T1H, WHc, bc, out, BSi, V_, D_, 1.f, false, false);
}

// round 11
// speedup vs baseline: 1.1388x; 1.0662x over previous
#include <cuda_runtime.h>
#include <cuda_fp16.h>
#include <math.h>
#include <stdint.h>

// ---------------- problem constants ----------------
constexpr int B_  = 8;
constexpr int S_  = 4096;
constexpr int D_  = 768;
constexpr int H_  = 12;
constexpr int Wd  = 128;     // window
constexpr int L_  = 2;
constexpr int V_  = 512;
constexpr int FF_ = 3072;
constexpr int DH  = 64;      // D_/H_
constexpr int NB  = S_ / Wd; // 32
constexpr int BSi = B_ * S_; // 32768

// ---------------- scratch (device globals; no allocation allowed) ----------------
__device__ float  g_X  [(size_t)BSi * D_];   // fp32 residual stream
__device__ __half g_XH [(size_t)BSi * D_];   // half copy (GEMM A input)
__device__ float  g_Q  [(size_t)BSi * D_];
__device__ float  g_K  [(size_t)BSi * D_];
__device__ float  g_V  [(size_t)BSi * D_];
__device__ __half g_ATTH[(size_t)BSi * D_];  // attention out (half, feeds Wo)
__device__ float  g_T1 [(size_t)BSi * D_];
__device__ __half g_T1H[(size_t)BSi * D_];
__device__ __half g_HH [(size_t)BSi * FF_];  // FF intermediate (half)
// half weights
__device__ __half g_WQKV[(size_t)L_ * 3 * D_ * D_]; // [L][2304][768]
__device__ float  g_bQKV[(size_t)L_ * 3 * D_];      // combined bias
__device__ __half g_WHo[(size_t)L_ * D_ * D_];
__device__ __half g_WH1[(size_t)L_ * FF_ * D_];
__device__ __half g_WH2[(size_t)L_ * FF_ * D_];
__device__ __half g_WHc[(size_t)V_ * D_];

// ---------------- helpers ----------------
__device__ __forceinline__ uint32_t smem_u32(const void* p) {
    uint32_t a;
    asm("{ .reg .u64 t; cvta.to.shared.u64 t, %1; cvt.u32.u64 %0, t; }" : "=r"(a) : "l"(p));
    return a;
}
__device__ __forceinline__ float warp_sum(float v) {
    #pragma unroll
    for (int o = 16; o > 0; o >>= 1) v += __shfl_xor_sync(0xffffffffu, v, o);
    return v;
}
__device__ __forceinline__ float warp_max(float v) {
    #pragma unroll
    for (int o = 16; o > 0; o >>= 1) v = fmaxf(v, __shfl_xor_sync(0xffffffffu, v, o));
    return v;
}
__device__ __forceinline__ void mma_f16(float* c, const uint32_t* a, const uint32_t* b) {
    asm volatile(
        "mma.sync.aligned.m16n8k16.row.col.f32.f16.f16.f32 "
        "{%0,%1,%2,%3}, {%4,%5,%6,%7}, {%8,%9}, {%0,%1,%2,%3};"
        : "+f"(c[0]), "+f"(c[1]), "+f"(c[2]), "+f"(c[3])
        : "r"(a[0]), "r"(a[1]), "r"(a[2]), "r"(a[3]), "r"(b[0]), "r"(b[1]));
}
#define CP_ASYNC16(dst, src) \
    asm volatile("cp.async.cg.shared.global [%0], [%1], 16;" :: "r"(dst), "l"(src))
#define CP_COMMIT() asm volatile("cp.async.commit_group;" ::: "memory")

typedef unsigned long long u64t;
#define PACK2(d, lo, hi) asm("mov.b64 %0, {%1,%2};" : "=l"(d) : "f"(lo), "f"(hi))
#define UNPACK2(lo, hi, s) asm("mov.b64 {%0,%1}, %2;" : "=f"(lo), "=f"(hi) : "l"(s))
#define FFMA2(d, a, b) asm("fma.rn.f32x2 %0, %1, %2, %0;" : "+l"(d) : "l"(a), "l"(b))
#define FMUL2(d, a, b) asm("mul.rn.f32x2 %0, %1, %2;" : "=l"(d) : "l"(a), "l"(b))

// ================= fp16 tensor-core GEMM (GKC=64: half the barriers) ==========
// Tile 128x256x64, 256 threads (8 warps, 2m x 4n, warp tile 64x64),
// 3-stage cp.async ring, ONE __syncthreads per 64-deep k-step (12 steps @K=768).
constexpr int GTM = 128, GTN = 256, GKC = 64, GSTG = 3;
constexpr int HSTRIDE = 72;                       // halves per smem row (64 + 8 pad)
constexpr int A_H = GTM * HSTRIDE;                // 9216 halves
constexpr int B_H = GTN * HSTRIDE;                // 18432 halves
constexpr int STAGE_H = A_H + B_H;                // 27648 halves
constexpr int GEMM_SMEM = GSTG * STAGE_H * 2;     // 165888 bytes

// shared mainloop pieces as a macro over local names
#define GEMM_PROLOGUE() \
    extern __shared__ __half smh[]; \
    const int tid = threadIdx.x, wid = tid >> 5, lane = tid & 31; \
    const int g = lane >> 2, tig = lane & 3; \
    const int wm = (wid & 1) * 64; \
    const int wn = (wid >> 1) * 64; \
    const int tile_m = blockIdx.y * GTM, tile_n = blockIdx.x * GTN; \
    float c[4][8][4]; \
    _Pragma("unroll") \
    for (int i = 0; i < 4; i++) \
        _Pragma("unroll") \
        for (int j = 0; j < 8; j++) \
            _Pragma("unroll") \
            for (int r = 0; r < 4; r++) c[i][j][r] = 0.f; \
    auto loadStage = [&](int st, int k0) { \
        __half* base = smh + st * STAGE_H; \
        _Pragma("unroll") \
        for (int i = 0; i < 4; i++) { \
            int ch = tid + i * 256;               /* A: 1024 chunks of 16B */ \
            int r = ch >> 3, cc = ch & 7; \
            CP_ASYNC16(smem_u32(base + r * HSTRIDE + cc * 8), \
                       A + (size_t)(tile_m + r) * K + k0 + cc * 8); \
        } \
        _Pragma("unroll") \
        for (int i = 0; i < 8; i++) { \
            int ch = tid + i * 256;               /* B: 2048 chunks of 16B */ \
            int r = ch >> 3, cc = ch & 7; \
            CP_ASYNC16(smem_u32(base + A_H + r * HSTRIDE + cc * 8), \
                       Bw + (size_t)(tile_n + r) * K + k0 + cc * 8); \
        } \
    }; \
    auto compute = [&](int st) { \
        const uint32_t* Aw = (const uint32_t*)(smh + st * STAGE_H); \
        const uint32_t* Bv = (const uint32_t*)(smh + st * STAGE_H + A_H); \
        _Pragma("unroll") \
        for (int kk = 0; kk < 4; kk++) { \
            uint32_t af[4][4], bf[8][2]; \
            _Pragma("unroll") \
            for (int mm = 0; mm < 4; mm++) { \
                const uint32_t* p = Aw + (wm + mm * 16 + g) * 36 + kk * 8 + tig; \
                af[mm][0] = p[0]; \
                af[mm][1] = p[8 * 36]; \
                af[mm][2] = p[4]; \
                af[mm][3] = p[8 * 36 + 4]; \
            } \
            _Pragma("unroll") \
            for (int nn = 0; nn < 8; nn++) { \
                const uint32_t* p = Bv + (wn + nn * 8 + g) * 36 + kk * 8 + tig; \
                bf[nn][0] = p[0]; \
                bf[nn][1] = p[4]; \
            } \
            _Pragma("unroll") \
            for (int mm = 0; mm < 4; mm++) \
                _Pragma("unroll") \
                for (int nn = 0; nn < 8; nn++) \
                    mma_f16(c[mm][nn], af[mm], bf[nn]); \
        } \
    }; \
    const int NK = K / GKC; \
    loadStage(0, 0);   CP_COMMIT(); \
    loadStage(1, GKC); CP_COMMIT(); \
    for (int ks = 0; ks < NK; ks++) { \
        if (ks + 1 == NK) { asm volatile("cp.async.wait_group 0;" ::: "memory"); } \
        else              { asm volatile("cp.async.wait_group 1;" ::: "memory"); } \
        __syncthreads(); \
        compute(ks % 3); \
        if (ks + 2 < NK) { loadStage((ks + 2) % 3, (ks + 2) * GKC); CP_COMMIT(); } \
    }

template<bool RELU, bool HOUT>
__global__ void __launch_bounds__(256) gemm_h_kernel(
    const __half* __restrict__ A, const __half* __restrict__ Bw,
    const float* __restrict__ bias, void* __restrict__ Cv,
    int M, int N, int K, float alpha)
{
    GEMM_PROLOGUE();

    #pragma unroll
    for (int mm = 0; mm < 4; mm++) {
        const int r0 = tile_m + wm + mm * 16 + g;
        #pragma unroll
        for (int nn = 0; nn < 8; nn++) {
            const int col = tile_n + wn + nn * 8 + 2 * tig;
            const float b0 = bias[col], b1 = bias[col + 1];
            float v0 = (c[mm][nn][0] + b0) * alpha;
            float v1 = (c[mm][nn][1] + b1) * alpha;
            float v2 = (c[mm][nn][2] + b0) * alpha;
            float v3 = (c[mm][nn][3] + b1) * alpha;
            if (RELU) {
                v0 = fmaxf(v0, 0.f); v1 = fmaxf(v1, 0.f);
                v2 = fmaxf(v2, 0.f); v3 = fmaxf(v3, 0.f);
            }
            if (HOUT) {
                __half* C = (__half*)Cv;
                *(__half2*)(C + (size_t)r0 * N + col)       = __floats2half2_rn(v0, v1);
                *(__half2*)(C + (size_t)(r0 + 8) * N + col) = __floats2half2_rn(v2, v3);
            } else {
                float* C = (float*)Cv;
                *(float2*)(C + (size_t)r0 * N + col)       = make_float2(v0, v1);
                *(float2*)(C + (size_t)(r0 + 8) * N + col) = make_float2(v2, v3);
            }
        }
    }
}

// fused QKV GEMM: N = 2304, epilogue routes per 768-column region.
__global__ void __launch_bounds__(256) gemm_qkv_kernel(
    const __half* __restrict__ A, const __half* __restrict__ Bw,
    const float* __restrict__ bias,
    float* __restrict__ Qf, float* __restrict__ Kf, float* __restrict__ Vf,
    int M, int K)
{
    GEMM_PROLOGUE();

    const int region = tile_n / D_;                 // 0=Q, 1=K, 2=V
    const float alf = (region == 0) ? 0.125f : 1.0f;
    float* Cd = (region == 0) ? Qf : ((region == 1) ? Kf : Vf);
    const int ncol0 = tile_n - region * D_;

    #pragma unroll
    for (int mm = 0; mm < 4; mm++) {
        const int r0 = tile_m + wm + mm * 16 + g;
        #pragma unroll
        for (int nn = 0; nn < 8; nn++) {
            const int coln = wn + nn * 8 + 2 * tig;     // within tile
            const int colg = tile_n + coln;              // global (bias)
            const float b0 = bias[colg], b1 = bias[colg + 1];
            float v0 = (c[mm][nn][0] + b0) * alf;
            float v1 = (c[mm][nn][1] + b1) * alf;
            float v2 = (c[mm][nn][2] + b0) * alf;
            float v3 = (c[mm][nn][3] + b1) * alf;
            *(float2*)(Cd + (size_t)r0 * D_ + ncol0 + coln)       = make_float2(v0, v1);
            *(float2*)(Cd + (size_t)(r0 + 8) * D_ + ncol0 + coln) = make_float2(v2, v3);
        }
    }
}

// ================= fused weight conversion (single launch) =================
constexpr size_t DDq_  = (size_t)L_ * D_ * D_ / 4;   // quads per D*D weight set
constexpr size_t FDq_  = (size_t)L_ * FF_ * D_ / 4;
constexpr size_t CQ_   = (size_t)V_ * D_ / 4;
constexpr size_t BQ_   = (size_t)L_ * 3 * D_ / 4;    // bias quads
constexpr size_t CVT_E0 = 3 * DDq_;                  // Wq,Wk,Wv -> WQKV
constexpr size_t CVT_E1 = CVT_E0 + DDq_;             // Wo
constexpr size_t CVT_E2 = CVT_E1 + FDq_;             // W1
constexpr size_t CVT_E3 = CVT_E2 + FDq_;             // W2
constexpr size_t CVT_E4 = CVT_E3 + CQ_;              // Wc
constexpr size_t CVT_E5 = CVT_E4 + BQ_;              // bias pack
constexpr int CVT_BLOCKS = (int)((CVT_E5 + 255) / 256);

__device__ __forceinline__ void st_h4(__half* d, float4 f) {
    *(__half2*)(d)     = __floats2half2_rn(f.x, f.y);
    *(__half2*)(d + 2) = __floats2half2_rn(f.z, f.w);
}

__global__ void cvt_all_kernel(
    const float* __restrict__ Wq, const float* __restrict__ Wk,
    const float* __restrict__ Wv, const float* __restrict__ Wo,
    const float* __restrict__ W1, const float* __restrict__ W2,
    const float* __restrict__ Wc,
    const float* __restrict__ bq, const float* __restrict__ bk,
    const float* __restrict__ bv,
    __half* __restrict__ WQKV, __half* __restrict__ WHo,
    __half* __restrict__ WH1, __half* __restrict__ WH2,
    __half* __restrict__ WHc, float* __restrict__ bQKV)
{
    const size_t t = (size_t)blockIdx.x * 256 + threadIdx.x;
    constexpr size_t DD = (size_t)D_ * D_;
    if (t < CVT_E0) {
        const int s = (int)(t / DDq_);
        const size_t i = (t - (size_t)s * DDq_) * 4;
        const float* src = (s == 0) ? Wq : ((s == 1) ? Wk : Wv);
        const size_t l = i / DD, rem = i - l * DD;
        float4 f = *(const float4*)(src + i);
        st_h4(WQKV + l * (3 * DD) + (size_t)s * DD + rem, f);
    } else if (t < CVT_E1) {
        const size_t i = (t - CVT_E0) * 4;
        st_h4(WHo + i, *(const float4*)(Wo + i));
    } else if (t < CVT_E2) {
        const size_t i = (t - CVT_E1) * 4;
        st_h4(WH1 + i, *(const float4*)(W1 + i));
    } else if (t < CVT_E3) {
        const size_t i = (t - CVT_E2) * 4;
        st_h4(WH2 + i, *(const float4*)(W2 + i));
    } else if (t < CVT_E4) {
        const size_t i = (t - CVT_E3) * 4;
        st_h4(WHc + i, *(const float4*)(Wc + i));
    } else if (t < CVT_E5) {
        const size_t i = (t - CVT_E4) * 4;
        const size_t l = i / (3 * D_);
        const int j = (int)(i - l * (3 * D_));
        const float* src = (j < D_) ? (bq + l * D_ + j)
                        : (j < 2 * D_) ? (bk + l * D_ + (j - D_))
                                       : (bv + l * D_ + (j - 2 * D_));
        *(float4*)(bQKV + i) = *(const float4*)src;
    }
}

// ================= embedding gather (fp32 + fp16 copies) =================
__global__ void embed_kernel(const int* __restrict__ call,
                             const float* __restrict__ emb,
                             float* __restrict__ X, __half* __restrict__ XH)
{
    size_t row = blockIdx.x;
    int c = call[row];
    const float* src = emb + (size_t)c * D_;
    float*  dst  = X  + row * D_;
    __half* dsth = XH + row * D_;
    for (int d = threadIdx.x; d < D_; d += blockDim.x) {
        float v = src[d];
        dst[d]  = v;
        dsth[d] = __float2half_rn(v);
    }
}

// ================= fused residual add + LayerNorm (fp32 + optional fp16 out) ====
__global__ void __launch_bounds__(256) add_ln_kernel(
    const float* __restrict__ x, const float* __restrict__ a,
    const float* __restrict__ g, const float* __restrict__ beta,
    float* __restrict__ out, __half* __restrict__ outh)
{
    __shared__ float red[8];
    const int row = blockIdx.x;
    const int tid = threadIdx.x;
    const int lane = tid & 31, wid = tid >> 5;
    const float* xr = x + (size_t)row * D_;
    const float* ar = a ? (a + (size_t)row * D_) : nullptr;
    float v[3];
    float s = 0.f;
    #pragma unroll
    for (int i = 0; i < 3; i++) {
        int c = tid + i * 256;
        float val = xr[c];
        if (ar) val += ar[c];
        v[i] = val;
        s += val;
    }
    s = warp_sum(s);
    if (lane == 0) red[wid] = s;
    __syncthreads();
    float tot = 0.f;
    #pragma unroll
    for (int w = 0; w < 8; w++) tot += red[w];
    float mean = tot * (1.f / (float)D_);
    float s2 = 0.f;
    #pragma unroll
    for (int i = 0; i < 3; i++) { float d = v[i] - mean; s2 += d * d; }
    s2 = warp_sum(s2);
    __syncthreads();
    if (lane == 0) red[wid] = s2;
    __syncthreads();
    float tot2 = 0.f;
    #pragma unroll
    for (int w = 0; w < 8; w++) tot2 += red[w];
    float rs = rsqrtf(tot2 * (1.f / (float)D_) + 1e-5f);
    float*  orow = out  ? out  + (size_t)row * D_ : nullptr;
    __half* hrow = outh ? outh + (size_t)row * D_ : nullptr;
    #pragma unroll
    for (int i = 0; i < 3; i++) {
        int c = tid + i * 256;
        float val = (v[i] - mean) * rs * g[c] + beta[c];
        if (orow) orow[c] = val;
        if (hrow) hrow[c] = __float2half_rn(val);
    }
}

// ================= banded attention: chunked smem, warp-uniform iteration ======
constexpr int BCH      = 128;  // keys per chunk
constexpr int BSTRIDE  = 68;   // floats per smem row (16B aligned, padded)
constexpr int SMEM_BAND = 2 * BCH * BSTRIDE * (int)sizeof(float); // 69632

__global__ void __launch_bounds__(128) band_attn_kernel(
    const float* __restrict__ Qf, const float* __restrict__ Kf,
    const float* __restrict__ Vf, __half* __restrict__ O)
{
    extern __shared__ float smb[];
    float* Ks = smb;
    float* Vs = smb + BCH * BSTRIDE;

    const int n = blockIdx.x, h = blockIdx.y, b = blockIdx.z;
    const int i = threadIdx.x;
    const int qpos = n * Wd + i;

    u64t q2[32], acc2[32];
    {
        const ulonglong2* qp = (const ulonglong2*)(Qf + (((size_t)b * S_ + qpos) * H_ + h) * DH);
        #pragma unroll
        for (int c = 0; c < 16; c++) { ulonglong2 t = qp[c]; q2[2*c] = t.x; q2[2*c+1] = t.y; }
    }
    #pragma unroll
    for (int k = 0; k < 32; k++) acc2[k] = 0ull;
    float m = -1e30f, ssum = 0.f;

    // ---- global key 0 first (direct LDG, all lanes same row -> broadcast) ----
    {
        const ulonglong2* kr = (const ulonglong2*)(Kf + ((size_t)b * S_ * H_ + h) * DH);
        const ulonglong2* vr = (const ulonglong2*)(Vf + ((size_t)b * S_ * H_ + h) * DH);
        u64t s2 = 0ull;
        #pragma unroll
        for (int c = 0; c < 16; c++) {
            ulonglong2 kv = kr[c];
            FFMA2(s2, q2[2*c], kv.x);
            FFMA2(s2, q2[2*c+1], kv.y);
        }
        float sa, sb;
        UNPACK2(sa, sb, s2);
        float s = sa + sb;          // no bias on the global column
        m = s; ssum = 1.f;          // first key: p = 1
        #pragma unroll
        for (int c = 0; c < 16; c++) {
            ulonglong2 vv = vr[c];
            float lo, hi;
            UNPACK2(lo, hi, vv.x); PACK2(acc2[2*c],   lo, hi);
            UNPACK2(lo, hi, vv.y); PACK2(acc2[2*c+1], lo, hi);
        }
    }

    const int base = n * Wd - Wd;
    int lo = i, hi = i + 2 * Wd;
    if (n == 0 && lo < Wd) lo = Wd;
    if (hi > 383) hi = 383;
    if (n == NB - 1 && hi > 255) hi = 255;

    for (int c = 0; c < 3; c++) {
        if (n == 0 && c == 0) continue;
        if (n == NB - 1 && c == 2) continue;
        const int clo = c * BCH;
        __syncthreads();
        for (int t = i; t < BCH * 16; t += 128) {
            int row = t >> 4, col = t & 15;
            size_t gb = (((size_t)b * S_ + (base + clo + row)) * H_ + h) * DH + col * 4;
            *(float4*)(Ks + row * BSTRIDE + col * 4) = *(const float4*)(Kf + gb);
            *(float4*)(Vs + row * BSTRIDE + col * 4) = *(const float4*)(Vf + gb);
        }
        __syncthreads();

        int llo = lo > clo ? lo : clo;
        int lhi = hi < clo + BCH - 1 ? hi : clo + BCH - 1;
        int wlo = __shfl_sync(0xffffffffu, llo, 0);
        int whi = __shfl_sync(0xffffffffu, lhi, 31);
        for (int jj = wlo; jj <= whi; jj++) {
            if (jj < llo || jj > lhi) continue;
            const int row = jj - clo;
            const int pos = base + jj;
            const ulonglong2* kr = (const ulonglong2*)(Ks + row * BSTRIDE);
            u64t s2 = 0ull;
            #pragma unroll
            for (int cc = 0; cc < 16; cc++) {
                ulonglong2 kv = kr[cc];
                FFMA2(s2, q2[2*cc], kv.x);
                FFMA2(s2, q2[2*cc+1], kv.y);
            }
            float sa, sb;
            UNPACK2(sa, sb, s2);
            float s = sa + sb + ((pos == 0) ? -10000.f : 0.f);
            if (s > m) {
                float corr = __expf(m - s);
                u64t cc2; PACK2(cc2, corr, corr);
                ssum *= corr;
                #pragma unroll
                for (int k = 0; k < 32; k++) FMUL2(acc2[k], acc2[k], cc2);
                m = s;
            }
            float p = __expf(s - m);
            ssum += p;
            u64t pp; PACK2(pp, p, p);
            const ulonglong2* vr = (const ulonglong2*)(Vs + row * BSTRIDE);
            #pragma unroll
            for (int cc = 0; cc < 16; cc++) {
                ulonglong2 vv = vr[cc];
                FFMA2(acc2[2*cc],   pp, vv.x);
                FFMA2(acc2[2*cc+1], pp, vv.y);
            }
        }
    }

    float inv = 1.f / ssum;
    __half* op = O + (((size_t)b * S_ + qpos) * H_ + h) * DH;
    #pragma unroll
    for (int c = 0; c < 32; c++) {
        float lo2, hi2;
        UNPACK2(lo2, hi2, acc2[c]);
        *(__half2*)(op + 2 * c) = __floats2half2_rn(lo2 * inv, hi2 * inv);
    }
}

// ================= full attention for the global query (s = 0) =================
__global__ void __launch_bounds__(512) global_attn_kernel(
    const float* __restrict__ Q, const float* __restrict__ Kt,
    const float* __restrict__ Vt, __half* __restrict__ O)
{
    __shared__ float qs[DH];
    __shared__ float sc[S_];
    __shared__ float red[16];
    __shared__ float ob[512];
    const int h = blockIdx.x, b = blockIdx.y;
    const int tid = threadIdx.x;
    const int lane = tid & 31, wid = tid >> 5;
    if (tid < DH) qs[tid] = Q[(((size_t)b * S_) * H_ + h) * DH + tid];
    __syncthreads();
    float lm = -1e30f;
    for (int s = tid; s < S_; s += 512) {
        const float* kp = Kt + (((size_t)b * S_ + s) * H_ + h) * DH;
        float d0 = 0.f, d1 = 0.f, d2 = 0.f, d3 = 0.f;
        #pragma unroll
        for (int c = 0; c < 16; c++) {
            d0 = fmaf(qs[c*4+0], kp[c*4+0], d0); d1 = fmaf(qs[c*4+1], kp[c*4+1], d1);
            d2 = fmaf(qs[c*4+2], kp[c*4+2], d2); d3 = fmaf(qs[c*4+3], kp[c*4+3], d3);
        }
        float sv = (d0 + d1) + (d2 + d3);
        sc[s] = sv;
        lm = fmaxf(lm, sv);
    }
    lm = warp_max(lm);
    if (lane == 0) red[wid] = lm;
    __syncthreads();
    float gm = -1e30f;
    #pragma unroll
    for (int w = 0; w < 16; w++) gm = fmaxf(gm, red[w]);
    float ls = 0.f;
    for (int s = tid; s < S_; s += 512) {
        float p = __expf(sc[s] - gm);
        sc[s] = p;
        ls += p;
    }
    ls = warp_sum(ls);
    __syncthreads();
    if (lane == 0) red[wid] = ls;
    __syncthreads();
    float gs = 0.f;
    #pragma unroll
    for (int w = 0; w < 16; w++) gs += red[w];
    const int d = tid & 63, seg = tid >> 6;
    float acc = 0.f;
    const int s0 = seg * (S_ / 8), s1 = s0 + (S_ / 8);
    for (int s = s0; s < s1; s++)
        acc = fmaf(sc[s], Vt[(((size_t)b * S_ + s) * H_ + h) * DH + d], acc);
    ob[tid] = acc;
    __syncthreads();
    if (tid < DH) {
        float tot = 0.f;
        #pragma unroll
        for (int k = 0; k < 8; k++) tot += ob[d + 64 * k];
        O[(((size_t)b * S_) * H_ + h) * DH + tid] = __float2half_rn(tot / gs);
    }
}

// ================= host side =================
static void gemm_h(const __half* A, const __half* Bw, const float* bias, void* C,
                   int M, int N, int K, float alpha, bool relu, bool hout)
{
    dim3 grid(N / GTN, M / GTM);
    if (relu) {
        if (hout) gemm_h_kernel<true, true ><<<grid, 256, GEMM_SMEM>>>(A, Bw, bias, C, M, N, K, alpha);
        else      gemm_h_kernel<true, false><<<grid, 256, GEMM_SMEM>>>(A, Bw, bias, C, M, N, K, alpha);
    } else {
        if (hout) gemm_h_kernel<false, true ><<<grid, 256, GEMM_SMEM>>>(A, Bw, bias, C, M, N, K, alpha);
        else      gemm_h_kernel<false, false><<<grid, 256, GEMM_SMEM>>>(A, Bw, bias, C, M, N, K, alpha);
    }
}

extern "C" void kernel_launch(void* const* d_in, const int* in_sizes, int n_in,
                              void* d_out, int out_size)
{
    const int* call = (const int*)d_in[0];

    int e = 9;
    for (int i = 0; i < n_in; i++) {
        if (in_sizes[i] == V_ * D_) { e = i; break; }
    }
    const float* emb   = (const float*)d_in[e + 0];
    const float* Wq    = (const float*)d_in[e + 1];
    const float* bq    = (const float*)d_in[e + 2];
    const float* Wk    = (const float*)d_in[e + 3];
    const float* bk    = (const float*)d_in[e + 4];
    const float* Wv    = (const float*)d_in[e + 5];
    const float* bv    = (const float*)d_in[e + 6];
    const float* Wo    = (const float*)d_in[e + 7];
    const float* bo    = (const float*)d_in[e + 8];
    const float* W1    = (const float*)d_in[e + 9];
    const float* b1    = (const float*)d_in[e + 10];
    const float* W2    = (const float*)d_in[e + 11];
    const float* b2    = (const float*)d_in[e + 12];
    const float* g1    = (const float*)d_in[e + 13];
    const float* beta1 = (const float*)d_in[e + 14];
    const float* g2    = (const float*)d_in[e + 15];
    const float* beta2 = (const float*)d_in[e + 16];
    const float* gf    = (const float*)d_in[e + 17];
    const float* betaf = (const float*)d_in[e + 18];
    const float* Wc    = (const float*)d_in[e + 19];
    const float* bc    = (const float*)d_in[e + 20];
    float* out = (float*)d_out;

    float *X, *Qb, *Kb, *Vb, *T1, *bQKV;
    __half *XH, *ATTH, *T1H, *HH, *WQKV, *WHo, *WH1, *WH2, *WHc;
    cudaGetSymbolAddress((void**)&X,    g_X);
    cudaGetSymbolAddress((void**)&XH,   g_XH);
    cudaGetSymbolAddress((void**)&Qb,   g_Q);
    cudaGetSymbolAddress((void**)&Kb,   g_K);
    cudaGetSymbolAddress((void**)&Vb,   g_V);
    cudaGetSymbolAddress((void**)&ATTH, g_ATTH);
    cudaGetSymbolAddress((void**)&T1,   g_T1);
    cudaGetSymbolAddress((void**)&T1H,  g_T1H);
    cudaGetSymbolAddress((void**)&HH,   g_HH);
    cudaGetSymbolAddress((void**)&WQKV, g_WQKV);
    cudaGetSymbolAddress((void**)&bQKV, g_bQKV);
    cudaGetSymbolAddress((void**)&WHo,  g_WHo);
    cudaGetSymbolAddress((void**)&WH1,  g_WH1);
    cudaGetSymbolAddress((void**)&WH2,  g_WH2);
    cudaGetSymbolAddress((void**)&WHc,  g_WHc);

    cudaFuncSetAttribute(gemm_h_kernel<false, false>,
                         cudaFuncAttributeMaxDynamicSharedMemorySize, GEMM_SMEM);
    cudaFuncSetAttribute(gemm_h_kernel<false, true>,
                         cudaFuncAttributeMaxDynamicSharedMemorySize, GEMM_SMEM);
    cudaFuncSetAttribute(gemm_h_kernel<true, false>,
                         cudaFuncAttributeMaxDynamicSharedMemorySize, GEMM_SMEM);
    cudaFuncSetAttribute(gemm_h_kernel<true, true>,
                         cudaFuncAttributeMaxDynamicSharedMemorySize, GEMM_SMEM);
    cudaFuncSetAttribute(gemm_qkv_kernel,
                         cudaFuncAttributeMaxDynamicSharedMemorySize, GEMM_SMEM);
    cudaFuncSetAttribute(band_attn_kernel,
                         cudaFuncAttributeMaxDynamicSharedMemorySize, SMEM_BAND);

    // launch 1: all weight conversions + QKV pack + bias pack
    cvt_all_kernel<<<CVT_BLOCKS, 256>>>(Wq, Wk, Wv, Wo, W1, W2, Wc, bq, bk, bv,
                                        WQKV, WHo, WH1, WH2, WHc, bQKV);
    // launch 2: embedding
    embed_kernel<<<BSi, 256>>>(call, emb, X, XH);

    const dim3 gAttn(NB, H_, B_);
    const dim3 gGlob(H_, B_);
    const dim3 gQKV(3 * D_ / GTN, BSi / GTM);   // 9 x 256
    const size_t DD = (size_t)D_ * D_;
    const size_t FD = (size_t)FF_ * D_;

    for (int l = 0; l < L_; l++) {
        gemm_qkv_kernel<<<gQKV, 256, GEMM_SMEM>>>(
            XH, WQKV + (size_t)l * 3 * DD, bQKV + (size_t)l * 3 * D_,
            Qb, Kb, Vb, BSi, D_);

        band_attn_kernel<<<gAttn, 128, SMEM_BAND>>>(Qb, Kb, Vb, ATTH);
        global_attn_kernel<<<gGlob, 512>>>(Qb, Kb, Vb, ATTH);

        gemm_h(ATTH, WHo + l * DD, bo + l * D_, T1, BSi, D_, D_, 1.f, false, false);
        add_ln_kernel<<<BSi, 256>>>(X, T1, g1 + l * D_, beta1 + l * D_, X, XH);

        gemm_h(XH, WH1 + l * FD, b1 + l * FF_, HH, BSi, FF_, D_, 1.f, true, true);
        gemm_h(HH, WH2 + l * FD, b2 + l * D_, T1, BSi, D_, FF_, 1.f, false, false);
        add_ln_kernel<<<BSi, 256>>>(X, T1, g2 + l * D_, beta2 + l * D_, X, XH);
    }

    add_ln_kernel<<<BSi, 256>>>(X, nullptr, gf, betaf, nullptr, T1H);
    gemm_h(T1H, WHc, bc, out, BSi, V_, D_, 1.f, false, false);
}

// round 12
// speedup vs baseline: 1.1389x; 1.0001x over previous
#include <cuda_runtime.h>
#include <cuda_fp16.h>
#include <math.h>
#include <stdint.h>

// ---------------- problem constants ----------------
constexpr int B_  = 8;
constexpr int S_  = 4096;
constexpr int D_  = 768;
constexpr int H_  = 12;
constexpr int Wd  = 128;     // window
constexpr int L_  = 2;
constexpr int V_  = 512;
constexpr int FF_ = 3072;
constexpr int DH  = 64;      // D_/H_
constexpr int NB  = S_ / Wd; // 32
constexpr int BSi = B_ * S_; // 32768

// ---------------- scratch (device globals; no allocation allowed) ----------------
__device__ float  g_X  [(size_t)BSi * D_];   // fp32 residual stream
__device__ __half g_XH [(size_t)BSi * D_];   // half copy (GEMM A input)
__device__ float  g_Q  [(size_t)BSi * D_];
__device__ float  g_K  [(size_t)BSi * D_];
__device__ float  g_V  [(size_t)BSi * D_];
__device__ __half g_ATTH[(size_t)BSi * D_];  // attention out (half, feeds Wo)
__device__ float  g_T1 [(size_t)BSi * D_];
__device__ __half g_T1H[(size_t)BSi * D_];
__device__ __half g_HH [(size_t)BSi * FF_];  // FF intermediate (half)
// half weights
__device__ __half g_WQKV[(size_t)L_ * 3 * D_ * D_]; // [L][2304][768]
__device__ float  g_bQKV[(size_t)L_ * 3 * D_];      // combined bias
__device__ __half g_WHo[(size_t)L_ * D_ * D_];
__device__ __half g_WH1[(size_t)L_ * FF_ * D_];
__device__ __half g_WH2[(size_t)L_ * FF_ * D_];
__device__ __half g_WHc[(size_t)V_ * D_];

// ---------------- helpers ----------------
__device__ __forceinline__ uint32_t smem_u32(const void* p) {
    uint32_t a;
    asm("{ .reg .u64 t; cvta.to.shared.u64 t, %1; cvt.u32.u64 %0, t; }" : "=r"(a) : "l"(p));
    return a;
}
__device__ __forceinline__ float warp_sum(float v) {
    #pragma unroll
    for (int o = 16; o > 0; o >>= 1) v += __shfl_xor_sync(0xffffffffu, v, o);
    return v;
}
__device__ __forceinline__ float warp_max(float v) {
    #pragma unroll
    for (int o = 16; o > 0; o >>= 1) v = fmaxf(v, __shfl_xor_sync(0xffffffffu, v, o));
    return v;
}
__device__ __forceinline__ void mma_f16(float* c, const uint32_t* a, const uint32_t* b) {
    asm volatile(
        "mma.sync.aligned.m16n8k16.row.col.f32.f16.f16.f32 "
        "{%0,%1,%2,%3}, {%4,%5,%6,%7}, {%8,%9}, {%0,%1,%2,%3};"
        : "+f"(c[0]), "+f"(c[1]), "+f"(c[2]), "+f"(c[3])
        : "r"(a[0]), "r"(a[1]), "r"(a[2]), "r"(a[3]), "r"(b[0]), "r"(b[1]));
}
#define CP_ASYNC16(dst, src) \
    asm volatile("cp.async.cg.shared.global [%0], [%1], 16;" :: "r"(dst), "l"(src))
#define CP_COMMIT() asm volatile("cp.async.commit_group;" ::: "memory")

typedef unsigned long long u64t;
#define PACK2(d, lo, hi) asm("mov.b64 %0, {%1,%2};" : "=l"(d) : "f"(lo), "f"(hi))
#define UNPACK2(lo, hi, s) asm("mov.b64 {%0,%1}, %2;" : "=f"(lo), "=f"(hi) : "l"(s))
#define FFMA2(d, a, b) asm("fma.rn.f32x2 %0, %1, %2, %0;" : "+l"(d) : "l"(a), "l"(b))
#define FMUL2(d, a, b) asm("mul.rn.f32x2 %0, %1, %2;" : "=l"(d) : "l"(a), "l"(b))

// ================= fp16 tensor-core GEMM (GKC=64: half the barriers) ==========
// Tile 128x256x64, 256 threads (8 warps, 2m x 4n, warp tile 64x64),
// 3-stage cp.async ring, ONE __syncthreads per 64-deep k-step (12 steps @K=768).
constexpr int GTM = 128, GTN = 256, GKC = 64, GSTG = 3;
constexpr int HSTRIDE = 72;                       // halves per smem row (64 + 8 pad)
constexpr int A_H = GTM * HSTRIDE;                // 9216 halves
constexpr int B_H = GTN * HSTRIDE;                // 18432 halves
constexpr int STAGE_H = A_H + B_H;                // 27648 halves
constexpr int GEMM_SMEM = GSTG * STAGE_H * 2;     // 165888 bytes

// shared mainloop pieces as a macro over local names
#define GEMM_PROLOGUE() \
    extern __shared__ __half smh[]; \
    const int tid = threadIdx.x, wid = tid >> 5, lane = tid & 31; \
    const int g = lane >> 2, tig = lane & 3; \
    const int wm = (wid & 1) * 64; \
    const int wn = (wid >> 1) * 64; \
    const int tile_m = blockIdx.y * GTM, tile_n = blockIdx.x * GTN; \
    float c[4][8][4]; \
    _Pragma("unroll") \
    for (int i = 0; i < 4; i++) \
        _Pragma("unroll") \
        for (int j = 0; j < 8; j++) \
            _Pragma("unroll") \
            for (int r = 0; r < 4; r++) c[i][j][r] = 0.f; \
    auto loadStage = [&](int st, int k0) { \
        __half* base = smh + st * STAGE_H; \
        _Pragma("unroll") \
        for (int i = 0; i < 4; i++) { \
            int ch = tid + i * 256;               /* A: 1024 chunks of 16B */ \
            int r = ch >> 3, cc = ch & 7; \
            CP_ASYNC16(smem_u32(base + r * HSTRIDE + cc * 8), \
                       A + (size_t)(tile_m + r) * K + k0 + cc * 8); \
        } \
        _Pragma("unroll") \
        for (int i = 0; i < 8; i++) { \
            int ch = tid + i * 256;               /* B: 2048 chunks of 16B */ \
            int r = ch >> 3, cc = ch & 7; \
            CP_ASYNC16(smem_u32(base + A_H + r * HSTRIDE + cc * 8), \
                       Bw + (size_t)(tile_n + r) * K + k0 + cc * 8); \
        } \
    }; \
    auto compute = [&](int st) { \
        const uint32_t* Aw = (const uint32_t*)(smh + st * STAGE_H); \
        const uint32_t* Bv = (const uint32_t*)(smh + st * STAGE_H + A_H); \
        _Pragma("unroll") \
        for (int kk = 0; kk < 4; kk++) { \
            uint32_t af[4][4], bf[8][2]; \
            _Pragma("unroll") \
            for (int mm = 0; mm < 4; mm++) { \
                const uint32_t* p = Aw + (wm + mm * 16 + g) * 36 + kk * 8 + tig; \
                af[mm][0] = p[0]; \
                af[mm][1] = p[8 * 36]; \
                af[mm][2] = p[4]; \
                af[mm][3] = p[8 * 36 + 4]; \
            } \
            _Pragma("unroll") \
            for (int nn = 0; nn < 8; nn++) { \
                const uint32_t* p = Bv + (wn + nn * 8 + g) * 36 + kk * 8 + tig; \
                bf[nn][0] = p[0]; \
                bf[nn][1] = p[4]; \
            } \
            _Pragma("unroll") \
            for (int mm = 0; mm < 4; mm++) \
                _Pragma("unroll") \
                for (int nn = 0; nn < 8; nn++) \
                    mma_f16(c[mm][nn], af[mm], bf[nn]); \
        } \
    }; \
    const int NK = K / GKC; \
    loadStage(0, 0);   CP_COMMIT(); \
    loadStage(1, GKC); CP_COMMIT(); \
    for (int ks = 0; ks < NK; ks++) { \
        if (ks + 1 == NK) { asm volatile("cp.async.wait_group 0;" ::: "memory"); } \
        else              { asm volatile("cp.async.wait_group 1;" ::: "memory"); } \
        __syncthreads(); \
        compute(ks % 3); \
        if (ks + 2 < NK) { loadStage((ks + 2) % 3, (ks + 2) * GKC); CP_COMMIT(); } \
    }

template<bool RELU, bool HOUT>
__global__ void __launch_bounds__(256) gemm_h_kernel(
    const __half* __restrict__ A, const __half* __restrict__ Bw,
    const float* __restrict__ bias, void* __restrict__ Cv,
    int M, int N, int K, float alpha)
{
    GEMM_PROLOGUE();

    #pragma unroll
    for (int mm = 0; mm < 4; mm++) {
        const int r0 = tile_m + wm + mm * 16 + g;
        #pragma unroll
        for (int nn = 0; nn < 8; nn++) {
            const int col = tile_n + wn + nn * 8 + 2 * tig;
            const float b0 = bias[col], b1 = bias[col + 1];
            float v0 = (c[mm][nn][0] + b0) * alpha;
            float v1 = (c[mm][nn][1] + b1) * alpha;
            float v2 = (c[mm][nn][2] + b0) * alpha;
            float v3 = (c[mm][nn][3] + b1) * alpha;
            if (RELU) {
                v0 = fmaxf(v0, 0.f); v1 = fmaxf(v1, 0.f);
                v2 = fmaxf(v2, 0.f); v3 = fmaxf(v3, 0.f);
            }
            if (HOUT) {
                __half* C = (__half*)Cv;
                *(__half2*)(C + (size_t)r0 * N + col)       = __floats2half2_rn(v0, v1);
                *(__half2*)(C + (size_t)(r0 + 8) * N + col) = __floats2half2_rn(v2, v3);
            } else {
                float* C = (float*)Cv;
                *(float2*)(C + (size_t)r0 * N + col)       = make_float2(v0, v1);
                *(float2*)(C + (size_t)(r0 + 8) * N + col) = make_float2(v2, v3);
            }
        }
    }
}

// fused QKV GEMM: N = 2304, epilogue routes per 768-column region.
__global__ void __launch_bounds__(256) gemm_qkv_kernel(
    const __half* __restrict__ A, const __half* __restrict__ Bw,
    const float* __restrict__ bias,
    float* __restrict__ Qf, float* __restrict__ Kf, float* __restrict__ Vf,
    int M, int K)
{
    GEMM_PROLOGUE();

    const int region = tile_n / D_;                 // 0=Q, 1=K, 2=V
    const float alf = (region == 0) ? 0.125f : 1.0f;
    float* Cd = (region == 0) ? Qf : ((region == 1) ? Kf : Vf);
    const int ncol0 = tile_n - region * D_;

    #pragma unroll
    for (int mm = 0; mm < 4; mm++) {
        const int r0 = tile_m + wm + mm * 16 + g;
        #pragma unroll
        for (int nn = 0; nn < 8; nn++) {
            const int coln = wn + nn * 8 + 2 * tig;     // within tile
            const int colg = tile_n + coln;              // global (bias)
            const float b0 = bias[colg], b1 = bias[colg + 1];
            float v0 = (c[mm][nn][0] + b0) * alf;
            float v1 = (c[mm][nn][1] + b1) * alf;
            float v2 = (c[mm][nn][2] + b0) * alf;
            float v3 = (c[mm][nn][3] + b1) * alf;
            *(float2*)(Cd + (size_t)r0 * D_ + ncol0 + coln)       = make_float2(v0, v1);
            *(float2*)(Cd + (size_t)(r0 + 8) * D_ + ncol0 + coln) = make_float2(v2, v3);
        }
    }
}

// ================= fused weight conversion (single launch) =================
constexpr size_t DDq_  = (size_t)L_ * D_ * D_ / 4;   // quads per D*D weight set
constexpr size_t FDq_  = (size_t)L_ * FF_ * D_ / 4;
constexpr size_t CQ_   = (size_t)V_ * D_ / 4;
constexpr size_t BQ_   = (size_t)L_ * 3 * D_ / 4;    // bias quads
constexpr size_t CVT_E0 = 3 * DDq_;                  // Wq,Wk,Wv -> WQKV
constexpr size_t CVT_E1 = CVT_E0 + DDq_;             // Wo
constexpr size_t CVT_E2 = CVT_E1 + FDq_;             // W1
constexpr size_t CVT_E3 = CVT_E2 + FDq_;             // W2
constexpr size_t CVT_E4 = CVT_E3 + CQ_;              // Wc
constexpr size_t CVT_E5 = CVT_E4 + BQ_;              // bias pack
constexpr int CVT_BLOCKS = (int)((CVT_E5 + 255) / 256);

__device__ __forceinline__ void st_h4(__half* d, float4 f) {
    *(__half2*)(d)     = __floats2half2_rn(f.x, f.y);
    *(__half2*)(d + 2) = __floats2half2_rn(f.z, f.w);
}

__global__ void cvt_all_kernel(
    const float* __restrict__ Wq, const float* __restrict__ Wk,
    const float* __restrict__ Wv, const float* __restrict__ Wo,
    const float* __restrict__ W1, const float* __restrict__ W2,
    const float* __restrict__ Wc,
    const float* __restrict__ bq, const float* __restrict__ bk,
    const float* __restrict__ bv,
    __half* __restrict__ WQKV, __half* __restrict__ WHo,
    __half* __restrict__ WH1, __half* __restrict__ WH2,
    __half* __restrict__ WHc, float* __restrict__ bQKV)
{
    const size_t t = (size_t)blockIdx.x * 256 + threadIdx.x;
    constexpr size_t DD = (size_t)D_ * D_;
    if (t < CVT_E0) {
        const int s = (int)(t / DDq_);
        const size_t i = (t - (size_t)s * DDq_) * 4;
        const float* src = (s == 0) ? Wq : ((s == 1) ? Wk : Wv);
        const size_t l = i / DD, rem = i - l * DD;
        float4 f = *(const float4*)(src + i);
        st_h4(WQKV + l * (3 * DD) + (size_t)s * DD + rem, f);
    } else if (t < CVT_E1) {
        const size_t i = (t - CVT_E0) * 4;
        st_h4(WHo + i, *(const float4*)(Wo + i));
    } else if (t < CVT_E2) {
        const size_t i = (t - CVT_E1) * 4;
        st_h4(WH1 + i, *(const float4*)(W1 + i));
    } else if (t < CVT_E3) {
        const size_t i = (t - CVT_E2) * 4;
        st_h4(WH2 + i, *(const float4*)(W2 + i));
    } else if (t < CVT_E4) {
        const size_t i = (t - CVT_E3) * 4;
        st_h4(WHc + i, *(const float4*)(Wc + i));
    } else if (t < CVT_E5) {
        const size_t i = (t - CVT_E4) * 4;
        const size_t l = i / (3 * D_);
        const int j = (int)(i - l * (3 * D_));
        const float* src = (j < D_) ? (bq + l * D_ + j)
                        : (j < 2 * D_) ? (bk + l * D_ + (j - D_))
                                       : (bv + l * D_ + (j - 2 * D_));
        *(float4*)(bQKV + i) = *(const float4*)src;
    }
}

// ================= embedding gather (fp32 + fp16 copies) =================
__global__ void embed_kernel(const int* __restrict__ call,
                             const float* __restrict__ emb,
                             float* __restrict__ X, __half* __restrict__ XH)
{
    size_t row = blockIdx.x;
    int c = call[row];
    const float* src = emb + (size_t)c * D_;
    float*  dst  = X  + row * D_;
    __half* dsth = XH + row * D_;
    for (int d = threadIdx.x; d < D_; d += blockDim.x) {
        float v = src[d];
        dst[d]  = v;
        dsth[d] = __float2half_rn(v);
    }
}

// ================= fused residual add + LayerNorm (fp32 + optional fp16 out) ====
__global__ void __launch_bounds__(256) add_ln_kernel(
    const float* __restrict__ x, const float* __restrict__ a,
    const float* __restrict__ g, const float* __restrict__ beta,
    float* __restrict__ out, __half* __restrict__ outh)
{
    __shared__ float red[8];
    const int row = blockIdx.x;
    const int tid = threadIdx.x;
    const int lane = tid & 31, wid = tid >> 5;
    const float* xr = x + (size_t)row * D_;
    const float* ar = a ? (a + (size_t)row * D_) : nullptr;
    float v[3];
    float s = 0.f;
    #pragma unroll
    for (int i = 0; i < 3; i++) {
        int c = tid + i * 256;
        float val = xr[c];
        if (ar) val += ar[c];
        v[i] = val;
        s += val;
    }
    s = warp_sum(s);
    if (lane == 0) red[wid] = s;
    __syncthreads();
    float tot = 0.f;
    #pragma unroll
    for (int w = 0; w < 8; w++) tot += red[w];
    float mean = tot * (1.f / (float)D_);
    float s2 = 0.f;
    #pragma unroll
    for (int i = 0; i < 3; i++) { float d = v[i] - mean; s2 += d * d; }
    s2 = warp_sum(s2);
    __syncthreads();
    if (lane == 0) red[wid] = s2;
    __syncthreads();
    float tot2 = 0.f;
    #pragma unroll
    for (int w = 0; w < 8; w++) tot2 += red[w];
    float rs = rsqrtf(tot2 * (1.f / (float)D_) + 1e-5f);
    float*  orow = out  ? out  + (size_t)row * D_ : nullptr;
    __half* hrow = outh ? outh + (size_t)row * D_ : nullptr;
    #pragma unroll
    for (int i = 0; i < 3; i++) {
        int c = tid + i * 256;
        float val = (v[i] - mean) * rs * g[c] + beta[c];
        if (orow) orow[c] = val;
        if (hrow) hrow[c] = __float2half_rn(val);
    }
}

// ================= banded attention: chunked smem, warp-uniform iteration ======
constexpr int BCH      = 128;  // keys per chunk
constexpr int BSTRIDE  = 68;   // floats per smem row (16B aligned, padded)
constexpr int SMEM_BAND = 2 * BCH * BSTRIDE * (int)sizeof(float); // 69632

__global__ void __launch_bounds__(128) band_attn_kernel(
    const float* __restrict__ Qf, const float* __restrict__ Kf,
    const float* __restrict__ Vf, __half* __restrict__ O)
{
    extern __shared__ float smb[];
    float* Ks = smb;
    float* Vs = smb + BCH * BSTRIDE;

    const int n = blockIdx.x, h = blockIdx.y, b = blockIdx.z;
    const int i = threadIdx.x;
    const int qpos = n * Wd + i;

    u64t q2[32], acc2[32];
    {
        const ulonglong2* qp = (const ulonglong2*)(Qf + (((size_t)b * S_ + qpos) * H_ + h) * DH);
        #pragma unroll
        for (int c = 0; c < 16; c++) { ulonglong2 t = qp[c]; q2[2*c] = t.x; q2[2*c+1] = t.y; }
    }
    #pragma unroll
    for (int k = 0; k < 32; k++) acc2[k] = 0ull;
    float m = -1e30f, ssum = 0.f;

    // ---- global key 0 first (direct LDG, all lanes same row -> broadcast) ----
    {
        const ulonglong2* kr = (const ulonglong2*)(Kf + ((size_t)b * S_ * H_ + h) * DH);
        const ulonglong2* vr = (const ulonglong2*)(Vf + ((size_t)b * S_ * H_ + h) * DH);
        u64t s2 = 0ull;
        #pragma unroll
        for (int c = 0; c < 16; c++) {
            ulonglong2 kv = kr[c];
            FFMA2(s2, q2[2*c], kv.x);
            FFMA2(s2, q2[2*c+1], kv.y);
        }
        float sa, sb;
        UNPACK2(sa, sb, s2);
        float s = sa + sb;          // no bias on the global column
        m = s; ssum = 1.f;          // first key: p = 1
        #pragma unroll
        for (int c = 0; c < 16; c++) {
            ulonglong2 vv = vr[c];
            float lo, hi;
            UNPACK2(lo, hi, vv.x); PACK2(acc2[2*c],   lo, hi);
            UNPACK2(lo, hi, vv.y); PACK2(acc2[2*c+1], lo, hi);
        }
    }

    const int base = n * Wd - Wd;
    int lo = i, hi = i + 2 * Wd;
    if (n == 0 && lo < Wd) lo = Wd;
    if (hi > 383) hi = 383;
    if (n == NB - 1 && hi > 255) hi = 255;

    for (int c = 0; c < 3; c++) {
        if (n == 0 && c == 0) continue;
        if (n == NB - 1 && c == 2) continue;
        const int clo = c * BCH;
        __syncthreads();
        for (int t = i; t < BCH * 16; t += 128) {
            int row = t >> 4, col = t & 15;
            size_t gb = (((size_t)b * S_ + (base + clo + row)) * H_ + h) * DH + col * 4;
            *(float4*)(Ks + row * BSTRIDE + col * 4) = *(const float4*)(Kf + gb);
            *(float4*)(Vs + row * BSTRIDE + col * 4) = *(const float4*)(Vf + gb);
        }
        __syncthreads();

        int llo = lo > clo ? lo : clo;
        int lhi = hi < clo + BCH - 1 ? hi : clo + BCH - 1;
        int wlo = __shfl_sync(0xffffffffu, llo, 0);
        int whi = __shfl_sync(0xffffffffu, lhi, 31);
        for (int jj = wlo; jj <= whi; jj++) {
            if (jj < llo || jj > lhi) continue;
            const int row = jj - clo;
            const int pos = base + jj;
            const ulonglong2* kr = (const ulonglong2*)(Ks + row * BSTRIDE);
            u64t s2 = 0ull;
            #pragma unroll
            for (int cc = 0; cc < 16; cc++) {
                ulonglong2 kv = kr[cc];
                FFMA2(s2, q2[2*cc], kv.x);
                FFMA2(s2, q2[2*cc+1], kv.y);
            }
            float sa, sb;
            UNPACK2(sa, sb, s2);
            float s = sa + sb + ((pos == 0) ? -10000.f : 0.f);
            if (s > m) {
                float corr = __expf(m - s);
                u64t cc2; PACK2(cc2, corr, corr);
                ssum *= corr;
                #pragma unroll
                for (int k = 0; k < 32; k++) FMUL2(acc2[k], acc2[k], cc2);
                m = s;
            }
            float p = __expf(s - m);
            ssum += p;
            u64t pp; PACK2(pp, p, p);
            const ulonglong2* vr = (const ulonglong2*)(Vs + row * BSTRIDE);
            #pragma unroll
            for (int cc = 0; cc < 16; cc++) {
                ulonglong2 vv = vr[cc];
                FFMA2(acc2[2*cc],   pp, vv.x);
                FFMA2(acc2[2*cc+1], pp, vv.y);
            }
        }
    }

    float inv = 1.f / ssum;
    __half* op = O + (((size_t)b * S_ + qpos) * H_ + h) * DH;
    #pragma unroll
    for (int c = 0; c < 32; c++) {
        float lo2, hi2;
        UNPACK2(lo2, hi2, acc2[c]);
        *(__half2*)(op + 2 * c) = __floats2half2_rn(lo2 * inv, hi2 * inv);
    }
}

// ================= full attention for the global query (s = 0) =================
__global__ void __launch_bounds__(512) global_attn_kernel(
    const float* __restrict__ Q, const float* __restrict__ Kt,
    const float* __restrict__ Vt, __half* __restrict__ O)
{
    __shared__ float qs[DH];
    __shared__ float sc[S_];
    __shared__ float red[16];
    __shared__ float ob[512];
    const int h = blockIdx.x, b = blockIdx.y;
    const int tid = threadIdx.x;
    const int lane = tid & 31, wid = tid >> 5;
    if (tid < DH) qs[tid] = Q[(((size_t)b * S_) * H_ + h) * DH + tid];
    __syncthreads();
    float lm = -1e30f;
    for (int s = tid; s < S_; s += 512) {
        const float* kp = Kt + (((size_t)b * S_ + s) * H_ + h) * DH;
        float d0 = 0.f, d1 = 0.f, d2 = 0.f, d3 = 0.f;
        #pragma unroll
        for (int c = 0; c < 16; c++) {
            d0 = fmaf(qs[c*4+0], kp[c*4+0], d0); d1 = fmaf(qs[c*4+1], kp[c*4+1], d1);
            d2 = fmaf(qs[c*4+2], kp[c*4+2], d2); d3 = fmaf(qs[c*4+3], kp[c*4+3], d3);
        }
        float sv = (d0 + d1) + (d2 + d3);
        sc[s] = sv;
        lm = fmaxf(lm, sv);
    }
    lm = warp_max(lm);
    if (lane == 0) red[wid] = lm;
    __syncthreads();
    float gm = -1e30f;
    #pragma unroll
    for (int w = 0; w < 16; w++) gm = fmaxf(gm, red[w]);
    float ls = 0.f;
    for (int s = tid; s < S_; s += 512) {
        float p = __expf(sc[s] - gm);
        sc[s] = p;
        ls += p;
    }
    ls = warp_sum(ls);
    __syncthreads();
    if (lane == 0) red[wid] = ls;
    __syncthreads();
    float gs = 0.f;
    #pragma unroll
    for (int w = 0; w < 16; w++) gs += red[w];
    const int d = tid & 63, seg = tid >> 6;
    float acc = 0.f;
    const int s0 = seg * (S_ / 8), s1 = s0 + (S_ / 8);
    for (int s = s0; s < s1; s++)
        acc = fmaf(sc[s], Vt[(((size_t)b * S_ + s) * H_ + h) * DH + d], acc);
    ob[tid] = acc;
    __syncthreads();
    if (tid < DH) {
        float tot = 0.f;
        #pragma unroll
        for (int k = 0; k < 8; k++) tot += ob[d + 64 * k];
        O[(((size_t)b * S_) * H_ + h) * DH + tid] = __float2half_rn(tot / gs);
    }
}

// ================= host side =================
static void gemm_h(const __half* A, const __half* Bw, const float* bias, void* C,
                   int M, int N, int K, float alpha, bool relu, bool hout)
{
    dim3 grid(N / GTN, M / GTM);
    if (relu) {
        if (hout) gemm_h_kernel<true, true ><<<grid, 256, GEMM_SMEM>>>(A, Bw, bias, C, M, N, K, alpha);
        else      gemm_h_kernel<true, false><<<grid, 256, GEMM_SMEM>>>(A, Bw, bias, C, M, N, K, alpha);
    } else {
        if (hout) gemm_h_kernel<false, true ><<<grid, 256, GEMM_SMEM>>>(A, Bw, bias, C, M, N, K, alpha);
        else      gemm_h_kernel<false, false><<<grid, 256, GEMM_SMEM>>>(A, Bw, bias, C, M, N, K, alpha);
    }
}

extern "C" void kernel_launch(void* const* d_in, const int* in_sizes, int n_in,
                              void* d_out, int out_size)
{
    const int* call = (const int*)d_in[0];

    int e = 9;
    for (int i = 0; i < n_in; i++) {
        if (in_sizes[i] == V_ * D_) { e = i; break; }
    }
    const float* emb   = (const float*)d_in[e + 0];
    const float* Wq    = (const float*)d_in[e + 1];
    const float* bq    = (const float*)d_in[e + 2];
    const float* Wk    = (const float*)d_in[e + 3];
    const float* bk    = (const float*)d_in[e + 4];
    const float* Wv    = (const float*)d_in[e + 5];
    const float* bv    = (const float*)d_in[e + 6];
    const float* Wo    = (const float*)d_in[e + 7];
    const float* bo    = (const float*)d_in[e + 8];
    const float* W1    = (const float*)d_in[e + 9];
    const float* b1    = (const float*)d_in[e + 10];
    const float* W2    = (const float*)d_in[e + 11];
    const float* b2    = (const float*)d_in[e + 12];
    const float* g1    = (const float*)d_in[e + 13];
    const float* beta1 = (const float*)d_in[e + 14];
    const float* g2    = (const float*)d_in[e + 15];
    const float* beta2 = (const float*)d_in[e + 16];
    const float* gf    = (const float*)d_in[e + 17];
    const float* betaf = (const float*)d_in[e + 18];
    const float* Wc    = (const float*)d_in[e + 19];
    const float* bc    = (const float*)d_in[e + 20];
    float* out = (float*)d_out;

    float *X, *Qb, *Kb, *Vb, *T1, *bQKV;
    __half *XH, *ATTH, *T1H, *HH, *WQKV, *WHo, *WH1, *WH2, *WHc;
    cudaGetSymbolAddress((void**)&X,    g_X);
    cudaGetSymbolAddress((void**)&XH,   g_XH);
    cudaGetSymbolAddress((void**)&Qb,   g_Q);
    cudaGetSymbolAddress((void**)&Kb,   g_K);
    cudaGetSymbolAddress((void**)&Vb,   g_V);
    cudaGetSymbolAddress((void**)&ATTH, g_ATTH);
    cudaGetSymbolAddress((void**)&T1,   g_T1);
    cudaGetSymbolAddress((void**)&T1H,  g_T1H);
    cudaGetSymbolAddress((void**)&HH,   g_HH);
    cudaGetSymbolAddress((void**)&WQKV, g_WQKV);
    cudaGetSymbolAddress((void**)&bQKV, g_bQKV);
    cudaGetSymbolAddress((void**)&WHo,  g_WHo);
    cudaGetSymbolAddress((void**)&WH1,  g_WH1);
    cudaGetSymbolAddress((void**)&WH2,  g_WH2);
    cudaGetSymbolAddress((void**)&WHc,  g_WHc);

    cudaFuncSetAttribute(gemm_h_kernel<false, false>,
                         cudaFuncAttributeMaxDynamicSharedMemorySize, GEMM_SMEM);
    cudaFuncSetAttribute(gemm_h_kernel<false, true>,
                         cudaFuncAttributeMaxDynamicSharedMemorySize, GEMM_SMEM);
    cudaFuncSetAttribute(gemm_h_kernel<true, false>,
                         cudaFuncAttributeMaxDynamicSharedMemorySize, GEMM_SMEM);
    cudaFuncSetAttribute(gemm_h_kernel<true, true>,
                         cudaFuncAttributeMaxDynamicSharedMemorySize, GEMM_SMEM);
    cudaFuncSetAttribute(gemm_qkv_kernel,
                         cudaFuncAttributeMaxDynamicSharedMemorySize, GEMM_SMEM);
    cudaFuncSetAttribute(band_attn_kernel,
                         cudaFuncAttributeMaxDynamicSharedMemorySize, SMEM_BAND);

    // launch 1: all weight conversions + QKV pack + bias pack
    cvt_all_kernel<<<CVT_BLOCKS, 256>>>(Wq, Wk, Wv, Wo, W1, W2, Wc, bq, bk, bv,
                                        WQKV, WHo, WH1, WH2, WHc, bQKV);
    // launch 2: embedding
    embed_kernel<<<BSi, 256>>>(call, emb, X, XH);

    const dim3 gAttn(NB, H_, B_);
    const dim3 gGlob(H_, B_);
    const dim3 gQKV(3 * D_ / GTN, BSi / GTM);   // 9 x 256
    const size_t DD = (size_t)D_ * D_;
    const size_t FD = (size_t)FF_ * D_;

    for (int l = 0; l < L_; l++) {
        gemm_qkv_kernel<<<gQKV, 256, GEMM_SMEM>>>(
            XH, WQKV + (size_t)l * 3 * DD, bQKV + (size_t)l * 3 * D_,
            Qb, Kb, Vb, BSi, D_);

        band_attn_kernel<<<gAttn, 128, SMEM_BAND>>>(Qb, Kb, Vb, ATTH);
        global_attn_kernel<<<gGlob, 512>>>(Qb, Kb, Vb, ATTH);

        gemm_h(ATTH, WHo + l * DD, bo + l * D_, T1, BSi, D_, D_, 1.f, false, false);
        add_ln_kernel<<<BSi, 256>>>(X, T1, g1 + l * D_, beta1 + l * D_, X, XH);

        gemm_h(XH, WH1 + l * FD, b1 + l * FF_, HH, BSi, FF_, D_, 1.f, true, true);
        gemm_h(HH, WH2 + l * FD, b2 + l * D_, T1, BSi, D_, FF_, 1.f, false, false);
        add_ln_kernel<<<BSi, 256>>>(X, T1, g2 + l * D_, beta2 + l * D_, X, XH);
    }

    add_ln_kernel<<<BSi, 256>>>(X, nullptr, gf, betaf, nullptr, T1H);
    gemm_h(T1H, WHc, bc, out, BSi, V_, D_, 1.f, false, false);
}